// round 11
// baseline (speedup 1.0000x reference)
#include <cuda_runtime.h>
#include <cuda_fp16.h>
#include <cstdint>

#define N_NODES 50000
#define N_EDGES 800000
#define E_TOT   (N_EDGES + N_NODES)
#define NCOLS   256
#define SLOPE   0.2f
#define NBLK    ((N_NODES + 255) / 256)   // 196 scan blocks

// ---------------- scratch (device globals) -----------------------------------
__device__ __half g_h[N_NODES * NCOLS];
__device__ __half g_xh[N_NODES * NCOLS];
__device__ __half g_bt1[256 * 128];
__device__ __half g_bt2[256 * 256];
__device__ __half g_bt3[256 * 256];
__device__ float  g_asrc[N_NODES * 4];
__device__ float  g_adst[N_NODES * 4];
__device__ int    g_counts[N_NODES];
__device__ int    g_bsum[256];
__device__ int    g_rowptr[N_NODES + 1];
__device__ int    g_cursor[N_NODES];
__device__ int    g_csr_src[E_TOT];

__device__ __forceinline__ void cpa16(uint32_t sdst, const void* gsrc, int srcsize) {
    asm volatile("cp.async.cg.shared.global [%0], [%1], 16, %2;"
                 :: "r"(sdst), "l"(gsrc), "r"(srcsize));
}

// ---------------- CSR build (fast path) ------------------------------------------
__global__ void hist_k(const int* __restrict__ ei) {
    int q = blockIdx.x * blockDim.x + threadIdx.x;
    if (q * 4 >= N_EDGES) return;
    int4 d4 = *(const int4*)(ei + N_EDGES + q * 4);
    atomicAdd(&g_counts[d4.x], 1);
    atomicAdd(&g_counts[d4.y], 1);
    atomicAdd(&g_counts[d4.z], 1);
    atomicAdd(&g_counts[d4.w], 1);
}
__global__ void scanA_k() {
    __shared__ int sm[256];
    int i = blockIdx.x * 256 + threadIdx.x;
    int v = (i < N_NODES) ? g_counts[i] + 1 : 0;
    sm[threadIdx.x] = v;
    __syncthreads();
    for (int o = 128; o; o >>= 1) {
        if (threadIdx.x < o) sm[threadIdx.x] += sm[threadIdx.x + o];
        __syncthreads();
    }
    if (threadIdx.x == 0) g_bsum[blockIdx.x] = sm[0];
}
__global__ void scanB_k() {
    __shared__ int sm[256];
    int t = threadIdx.x;
    int v = (t < NBLK) ? g_bsum[t] : 0;
    sm[t] = v;
    __syncthreads();
    for (int o = 1; o < 256; o <<= 1) {
        int u = (t >= o) ? sm[t - o] : 0;
        __syncthreads();
        sm[t] += u;
        __syncthreads();
    }
    g_bsum[t] = sm[t] - v;
}
__global__ void scanC_k() {
    __shared__ int sm[256];
    int t = threadIdx.x;
    int i = blockIdx.x * 256 + t;
    int v = (i < N_NODES) ? g_counts[i] + 1 : 0;
    sm[t] = v;
    __syncthreads();
    for (int o = 1; o < 256; o <<= 1) {
        int u = (t >= o) ? sm[t - o] : 0;
        __syncthreads();
        sm[t] += u;
        __syncthreads();
    }
    if (i < N_NODES) {
        int off = g_bsum[blockIdx.x] + sm[t] - v;
        g_rowptr[i] = off;
        g_csr_src[off] = i;
        g_cursor[i] = off + 1;
    }
    if (i == 0) g_rowptr[N_NODES] = E_TOT;
}
__global__ void scatter_k(const int* __restrict__ ei) {
    int q = blockIdx.x * blockDim.x + threadIdx.x;
    if (q * 4 >= N_EDGES) return;
    int4 s4 = *(const int4*)(ei + q * 4);
    int4 d4 = *(const int4*)(ei + N_EDGES + q * 4);
    g_csr_src[atomicAdd(&g_cursor[d4.x], 1)] = s4.x;
    g_csr_src[atomicAdd(&g_cursor[d4.y], 1)] = s4.y;
    g_csr_src[atomicAdd(&g_cursor[d4.z], 1)] = s4.z;
    g_csr_src[atomicAdd(&g_cursor[d4.w], 1)] = s4.w;
}

// ---------------- prep kernels ---------------------------------------------------
__global__ void transpose_h_k(const float* __restrict__ W, __half* __restrict__ Bt, int K) {
    int idx = blockIdx.x * blockDim.x + threadIdx.x;
    if (idx >= 256 * K) return;
    int n = idx / K, k = idx - n * K;
    Bt[idx] = __float2half_rn(W[k * 256 + n]);
}
__global__ void transpose2_h_k(const float* __restrict__ W2, __half* __restrict__ Bt2,
                               const float* __restrict__ W3, __half* __restrict__ Bt3) {
    int idx = blockIdx.x * blockDim.x + threadIdx.x;
    const float* W = W2;
    __half* Bt = Bt2;
    if (idx >= 256 * 256) { idx -= 256 * 256; W = W3; Bt = Bt3; }
    int n = idx >> 8, k = idx & 255;
    Bt[idx] = __float2half_rn(W[k * 256 + n]);
}
__global__ void tohalf_k(const float* __restrict__ in, __half* __restrict__ o, int n) {
    int i = blockIdx.x * blockDim.x + threadIdx.x;
    if (i < n) o[i] = __float2half_rn(in[i]);
}

// ---------------- 3-stage cp.async fp16 GEMM, tile 128x256, 512 threads ----------
// 4x4 warp grid: warp tile 32x64 (one head per warp column band).
#define SMS_H 40
#define TILE_AH (128 * SMS_H)
#define TILE_BH (256 * SMS_H)
#define STAGES 3
#define GEMM_SMEM (STAGES * (TILE_AH + TILE_BH) * 2)   // 92160 B

__global__ __launch_bounds__(512, 1) void gemm_mma(
    const __half* __restrict__ A, const __half* __restrict__ Bt,
    __half* __restrict__ C,
    const float* __restrict__ avs, const float* __restrict__ avd,
    int M, int K)
{
    extern __shared__ __half smh[];
    __half* Abuf = smh;
    __half* Bbuf = smh + STAGES * TILE_AH;
    uint32_t sA0 = (uint32_t)__cvta_generic_to_shared(Abuf);
    uint32_t sB0 = (uint32_t)__cvta_generic_to_shared(Bbuf);

    int t = threadIdx.x;
    int lane = t & 31, wid = t >> 5;
    int wm = wid & 3, wn = wid >> 2;     // 4 x 4 warp grid, warp tile 32x64
    int g = lane >> 2, tg = lane & 3;
    int row0 = blockIdx.x * 128;

    const int nch = K >> 5;

    auto issue = [&](int kc, int stg) {
        int k0 = kc << 5;
        uint32_t sa = sA0 + stg * (TILE_AH * 2);
        uint32_t sb = sB0 + stg * (TILE_BH * 2);
        {   // A: 128 rows x 2 x 16B = 512 copies, one per thread
            int r = t >> 2, c8 = (t & 3) << 3;
            int gr = row0 + r;
            const __half* srcA = A + (size_t)min(gr, M - 1) * K + k0 + c8;
            cpa16(sa + (r * SMS_H + c8) * 2, srcA, gr < M ? 16 : 0);
        }
#pragma unroll
        for (int i = 0; i < 2; i++) {    // B: 256 rows x 2 x 16B = 1024 copies
            int idx = t + (i << 9);
            int r = idx >> 2, c8 = (idx & 3) << 3;
            const __half* srcB = Bt + (size_t)r * K + k0 + c8;
            cpa16(sb + (r * SMS_H + c8) * 2, srcB, 16);
        }
        asm volatile("cp.async.commit_group;" ::: "memory");
    };

    float c[2][8][4] = {};
    issue(0, 0);
    issue(1, 1);

    for (int kc = 0; kc < nch; kc++) {
        int stg = kc % STAGES;
        if (kc + 2 < nch) {
            issue(kc + 2, (kc + 2) % STAGES);
            asm volatile("cp.async.wait_group 2;" ::: "memory");
        } else if (kc + 1 < nch) {
            asm volatile("cp.async.wait_group 1;" ::: "memory");
        } else {
            asm volatile("cp.async.wait_group 0;" ::: "memory");
        }
        __syncthreads();
        const __half* Ab = Abuf + stg * TILE_AH;
        const __half* Bb = Bbuf + stg * TILE_BH;
#pragma unroll
        for (int ks = 0; ks < 2; ks++) {
            int kb = ks * 16;
            uint32_t a[2][4], b[8][2];
#pragma unroll
            for (int mf = 0; mf < 2; mf++) {
                int r = wm * 32 + mf * 16 + g;
                a[mf][0] = *(const uint32_t*)&Ab[r * SMS_H + kb + 2 * tg];
                a[mf][1] = *(const uint32_t*)&Ab[(r + 8) * SMS_H + kb + 2 * tg];
                a[mf][2] = *(const uint32_t*)&Ab[r * SMS_H + kb + 2 * tg + 8];
                a[mf][3] = *(const uint32_t*)&Ab[(r + 8) * SMS_H + kb + 2 * tg + 8];
            }
#pragma unroll
            for (int nf = 0; nf < 8; nf++) {
                int n = wn * 64 + nf * 8 + g;
                b[nf][0] = *(const uint32_t*)&Bb[n * SMS_H + kb + 2 * tg];
                b[nf][1] = *(const uint32_t*)&Bb[n * SMS_H + kb + 2 * tg + 8];
            }
#pragma unroll
            for (int mf = 0; mf < 2; mf++)
#pragma unroll
                for (int nf = 0; nf < 8; nf++)
                    asm volatile(
                        "mma.sync.aligned.m16n8k16.row.col.f32.f16.f16.f32 "
                        "{%0,%1,%2,%3}, {%4,%5,%6,%7}, {%8,%9}, {%0,%1,%2,%3};"
                        : "+f"(c[mf][nf][0]), "+f"(c[mf][nf][1]),
                          "+f"(c[mf][nf][2]), "+f"(c[mf][nf][3])
                        : "r"(a[mf][0]), "r"(a[mf][1]), "r"(a[mf][2]), "r"(a[mf][3]),
                          "r"(b[nf][0]), "r"(b[nf][1]));
        }
        __syncthreads();
    }

    int head = wn;
#pragma unroll
    for (int mf = 0; mf < 2; mf++) {
        int r0 = row0 + wm * 32 + mf * 16 + g;
        int r1 = r0 + 8;
        float sv0 = 0.f, sv1 = 0.f, dv0 = 0.f, dv1 = 0.f;
#pragma unroll
        for (int nf = 0; nf < 8; nf++) {
            int col = wn * 64 + nf * 8 + tg * 2;
            float x0 = c[mf][nf][0], x1 = c[mf][nf][1];
            float x2 = c[mf][nf][2], x3 = c[mf][nf][3];
            if (r0 < M)
                *(__half2*)(C + (size_t)r0 * NCOLS + col) = __floats2half2_rn(x0, x1);
            if (r1 < M)
                *(__half2*)(C + (size_t)r1 * NCOLS + col) = __floats2half2_rn(x2, x3);
            float w0 = __ldg(avs + col), w1 = __ldg(avs + col + 1);
            float u0 = __ldg(avd + col), u1 = __ldg(avd + col + 1);
            sv0 += x0 * w0 + x1 * w1;
            sv1 += x2 * w0 + x3 * w1;
            dv0 += x0 * u0 + x1 * u1;
            dv1 += x2 * u0 + x3 * u1;
        }
        sv0 += __shfl_xor_sync(0xffffffffu, sv0, 1);
        sv0 += __shfl_xor_sync(0xffffffffu, sv0, 2);
        sv1 += __shfl_xor_sync(0xffffffffu, sv1, 1);
        sv1 += __shfl_xor_sync(0xffffffffu, sv1, 2);
        dv0 += __shfl_xor_sync(0xffffffffu, dv0, 1);
        dv0 += __shfl_xor_sync(0xffffffffu, dv0, 2);
        dv1 += __shfl_xor_sync(0xffffffffu, dv1, 1);
        dv1 += __shfl_xor_sync(0xffffffffu, dv1, 2);
        if (tg == 0) {
            if (r0 < M) { g_asrc[r0 * 4 + head] = sv0; g_adst[r0 * 4 + head] = dv0; }
            if (r1 < M) { g_asrc[r1 * 4 + head] = sv1; g_adst[r1 * 4 + head] = dv1; }
        }
    }
}

// ---------------- aggregation: one warp per dst, no-max softmax ------------------
__global__ __launch_bounds__(256) void aggr_k(
    const __half* __restrict__ h, const float* __restrict__ bias,
    __half* __restrict__ out_h, float* __restrict__ out_f)
{
    __shared__ float sw[8][128];
    int d    = (blockIdx.x * blockDim.x + threadIdx.x) >> 5;
    int lane = threadIdx.x & 31;
    int wblk = threadIdx.x >> 5;
    if (d >= N_NODES) return;
    int hol = lane >> 3;
    float* swp = sw[wblk];

    int beg = g_rowptr[d];
    int end = g_rowptr[d + 1];
    float4 adst4 = *(const float4*)(g_adst + d * 4);

    float wsum = 0.f;
    float4 acc0 = make_float4(0.f, 0.f, 0.f, 0.f);
    float4 acc1 = make_float4(0.f, 0.f, 0.f, 0.f);

    for (int base = beg; base < end; base += 32) {
        int i = base + lane;
        bool v = i < end;
        int s_l = v ? g_csr_src[i] : 0;
        float4 w4 = make_float4(0.f, 0.f, 0.f, 0.f);
        if (v) {
            float4 as4 = *(const float4*)(g_asrc + s_l * 4);
            float ex = as4.x + adst4.x, ey = as4.y + adst4.y;
            float ez = as4.z + adst4.z, ew = as4.w + adst4.w;
            ex = ex > 0.f ? ex : SLOPE * ex;
            ey = ey > 0.f ? ey : SLOPE * ey;
            ez = ez > 0.f ? ez : SLOPE * ez;
            ew = ew > 0.f ? ew : SLOPE * ew;
            w4.x = __expf(ex); w4.y = __expf(ey);
            w4.z = __expf(ez); w4.w = __expf(ew);
        }
        *(float4*)(swp + lane * 4) = w4;
        __syncwarp();

        int n = min(32, end - base);
        int j = 0;
        for (; j + 4 <= n; j += 4) {
            int s0 = __shfl_sync(0xffffffffu, s_l, j);
            int s1 = __shfl_sync(0xffffffffu, s_l, j + 1);
            int s2 = __shfl_sync(0xffffffffu, s_l, j + 2);
            int s3 = __shfl_sync(0xffffffffu, s_l, j + 3);
            float w0 = swp[j * 4 + hol];
            float w1 = swp[j * 4 + 4 + hol];
            float w2 = swp[j * 4 + 8 + hol];
            float w3 = swp[j * 4 + 12 + hol];
            wsum += (w0 + w1) + (w2 + w3);
            uint4 v0 = *(const uint4*)(h + (size_t)s0 * NCOLS + lane * 8);
            uint4 v1 = *(const uint4*)(h + (size_t)s1 * NCOLS + lane * 8);
            uint4 v2 = *(const uint4*)(h + (size_t)s2 * NCOLS + lane * 8);
            uint4 v3 = *(const uint4*)(h + (size_t)s3 * NCOLS + lane * 8);
            const __half2* p0 = (const __half2*)&v0;
            const __half2* p1 = (const __half2*)&v1;
            const __half2* p2 = (const __half2*)&v2;
            const __half2* p3 = (const __half2*)&v3;
#pragma unroll
            for (int q = 0; q < 2; q++) {
                float2 f0 = __half22float2(p0[q]), f0b = __half22float2(p0[q + 2]);
                float2 f1 = __half22float2(p1[q]), f1b = __half22float2(p1[q + 2]);
                float2 f2 = __half22float2(p2[q]), f2b = __half22float2(p2[q + 2]);
                float2 f3 = __half22float2(p3[q]), f3b = __half22float2(p3[q + 2]);
                float* a0 = (q == 0) ? &acc0.x : &acc0.z;
                float* a1 = (q == 0) ? &acc1.x : &acc1.z;
                a0[0] += w0 * f0.x + w1 * f1.x + w2 * f2.x + w3 * f3.x;
                a0[1] += w0 * f0.y + w1 * f1.y + w2 * f2.y + w3 * f3.y;
                a1[0] += w0 * f0b.x + w1 * f1b.x + w2 * f2b.x + w3 * f3b.x;
                a1[1] += w0 * f0b.y + w1 * f1b.y + w2 * f2b.y + w3 * f3b.y;
            }
        }
        for (; j < n; j++) {
            int s0 = __shfl_sync(0xffffffffu, s_l, j);
            float w0 = swp[j * 4 + hol];
            wsum += w0;
            uint4 v0 = *(const uint4*)(h + (size_t)s0 * NCOLS + lane * 8);
            const __half2* p0 = (const __half2*)&v0;
            float2 f0 = __half22float2(p0[0]);
            float2 f1 = __half22float2(p0[1]);
            float2 f2 = __half22float2(p0[2]);
            float2 f3 = __half22float2(p0[3]);
            acc0.x += w0 * f0.x; acc0.y += w0 * f0.y;
            acc0.z += w0 * f1.x; acc0.w += w0 * f1.y;
            acc1.x += w0 * f2.x; acc1.y += w0 * f2.y;
            acc1.z += w0 * f3.x; acc1.w += w0 * f3.y;
        }
        __syncwarp();
    }

    float inv = 1.f / wsum;
    int c0 = lane * 8;
    float4 bb0 = *(const float4*)(bias + c0);
    float4 bb1 = *(const float4*)(bias + c0 + 4);
    float o_[8];
    o_[0] = acc0.x * inv + bb0.x; o_[1] = acc0.y * inv + bb0.y;
    o_[2] = acc0.z * inv + bb0.z; o_[3] = acc0.w * inv + bb0.w;
    o_[4] = acc1.x * inv + bb1.x; o_[5] = acc1.y * inv + bb1.y;
    o_[6] = acc1.z * inv + bb1.z; o_[7] = acc1.w * inv + bb1.w;
#pragma unroll
    for (int k = 0; k < 8; k++) {
        float o = o_[k];
        o_[k] = o > 0.f ? o : (__expf(o) - 1.f);
    }
    if (out_h) {
        __half2 hh[4];
        hh[0] = __floats2half2_rn(o_[0], o_[1]);
        hh[1] = __floats2half2_rn(o_[2], o_[3]);
        hh[2] = __floats2half2_rn(o_[4], o_[5]);
        hh[3] = __floats2half2_rn(o_[6], o_[7]);
        *(uint4*)(out_h + (size_t)d * NCOLS + c0) = *(uint4*)hh;
    } else {
        *(float4*)(out_f + (size_t)d * NCOLS + c0)     = make_float4(o_[0], o_[1], o_[2], o_[3]);
        *(float4*)(out_f + (size_t)d * NCOLS + c0 + 4) = make_float4(o_[4], o_[5], o_[6], o_[7]);
    }
}

// ---------------- driver ---------------------------------------------------------
extern "C" void kernel_launch(void* const* d_in, const int* in_sizes, int n_in,
                              void* d_out, int out_size)
{
    const float* inp = (const float*)d_in[0];
    const int*   ei  = (const int*)d_in[1];
    const float* W1  = (const float*)d_in[2];
    const float* as1 = (const float*)d_in[3];
    const float* ad1 = (const float*)d_in[4];
    const float* b1  = (const float*)d_in[5];
    const float* W2  = (const float*)d_in[6];
    const float* as2 = (const float*)d_in[7];
    const float* ad2 = (const float*)d_in[8];
    const float* b2  = (const float*)d_in[9];
    const float* W3  = (const float*)d_in[10];
    const float* as3 = (const float*)d_in[11];
    const float* ad3 = (const float*)d_in[12];
    const float* b3  = (const float*)d_in[13];
    float* out = (float*)d_out;

    __half *hbuf, *xh, *bt1, *bt2, *bt3;
    int* counts;
    cudaGetSymbolAddress((void**)&hbuf, g_h);
    cudaGetSymbolAddress((void**)&xh, g_xh);
    cudaGetSymbolAddress((void**)&bt1, g_bt1);
    cudaGetSymbolAddress((void**)&bt2, g_bt2);
    cudaGetSymbolAddress((void**)&bt3, g_bt3);
    cudaGetSymbolAddress((void**)&counts, g_counts);

    cudaFuncSetAttribute(gemm_mma, cudaFuncAttributeMaxDynamicSharedMemorySize, GEMM_SMEM);

    static cudaStream_t s2 = nullptr;
    static cudaEvent_t e_fork = nullptr, e_join = nullptr;
    if (!s2) {
        cudaStreamCreateWithFlags(&s2, cudaStreamNonBlocking);
        cudaEventCreateWithFlags(&e_fork, cudaEventDisableTiming);
        cudaEventCreateWithFlags(&e_join, cudaEventDisableTiming);
    }

    int ggrid = (N_NODES + 127) / 128;
    int agrid = (N_NODES * 32 + 255) / 256;

    cudaEventRecord(e_fork, 0);

    // main stream: layer-1 prep + GEMM
    transpose_h_k<<<(256 * 128 + 255) / 256, 256>>>(W1, bt1, 128);
    tohalf_k<<<(N_NODES * 128 + 255) / 256, 256>>>(inp, xh, N_NODES * 128);
    gemm_mma<<<ggrid, 512, GEMM_SMEM>>>(xh, bt1, hbuf, as1, ad1, N_NODES, 128);

    // fork stream: CSR build + W2/W3 transposes (CSR chain first, unaffected)
    cudaStreamWaitEvent(s2, e_fork, 0);
    cudaMemsetAsync(counts, 0, N_NODES * sizeof(int), s2);
    hist_k<<<(N_EDGES / 4 + 255) / 256, 256, 0, s2>>>(ei);
    scanA_k<<<NBLK, 256, 0, s2>>>();
    scanB_k<<<1, 256, 0, s2>>>();
    scanC_k<<<NBLK, 256, 0, s2>>>();
    scatter_k<<<(N_EDGES / 4 + 255) / 256, 256, 0, s2>>>(ei);
    transpose2_h_k<<<(2 * 256 * 256 + 255) / 256, 256, 0, s2>>>(W2, bt2, W3, bt3);
    cudaEventRecord(e_join, s2);

    cudaStreamWaitEvent(0, e_join, 0);
    aggr_k<<<agrid, 256>>>(hbuf, b1, xh, nullptr);

    gemm_mma<<<ggrid, 512, GEMM_SMEM>>>(xh, bt2, hbuf, as2, ad2, N_NODES, 256);
    aggr_k<<<agrid, 256>>>(hbuf, b2, xh, nullptr);

    gemm_mma<<<ggrid, 512, GEMM_SMEM>>>(xh, bt3, hbuf, as3, ad3, N_NODES, 256);
    aggr_k<<<agrid, 256>>>(hbuf, b3, nullptr, out);
}

// round 12
// speedup vs baseline: 1.0124x; 1.0124x over previous
#include <cuda_runtime.h>
#include <cuda_fp16.h>
#include <cstdint>

#define N_NODES 50000
#define N_EDGES 800000
#define E_TOT   (N_EDGES + N_NODES)
#define NCOLS   256
#define SLOPE   0.2f
#define NBLK    ((N_NODES + 255) / 256)

// ---------------- scratch (device globals) -----------------------------------
__device__ __half g_h[N_NODES * NCOLS];
__device__ __half g_xh[N_NODES * NCOLS];
__device__ __half g_bt1[256 * 128];
__device__ __half g_bt2[256 * 256];
__device__ __half g_bt3[256 * 256];
__device__ float  g_asrc[N_NODES * 4];
__device__ float  g_adst[N_NODES * 4];
__device__ int    g_counts[N_NODES];
__device__ int    g_bsum[256];
__device__ int    g_rowptr[N_NODES + 1];
__device__ int    g_cursor[N_NODES];
__device__ int    g_csr_src[E_TOT];

__device__ __forceinline__ void cpa16(uint32_t sdst, const void* gsrc, int srcsize) {
    asm volatile("cp.async.cg.shared.global [%0], [%1], 16, %2;"
                 :: "r"(sdst), "l"(gsrc), "r"(srcsize));
}
#define LDSM_X4(r0, r1, r2, r3, addr) \
    asm volatile("ldmatrix.sync.aligned.m8n8.x4.shared.b16 {%0,%1,%2,%3}, [%4];" \
                 : "=r"(r0), "=r"(r1), "=r"(r2), "=r"(r3) : "r"(addr))

// ---------------- CSR build (fast path) ------------------------------------------
__global__ void hist_k(const int* __restrict__ ei) {
    int q = blockIdx.x * blockDim.x + threadIdx.x;
    if (q * 4 >= N_EDGES) return;
    int4 d4 = *(const int4*)(ei + N_EDGES + q * 4);
    atomicAdd(&g_counts[d4.x], 1);
    atomicAdd(&g_counts[d4.y], 1);
    atomicAdd(&g_counts[d4.z], 1);
    atomicAdd(&g_counts[d4.w], 1);
}
__global__ void scanA_k() {
    __shared__ int sm[256];
    int i = blockIdx.x * 256 + threadIdx.x;
    int v = (i < N_NODES) ? g_counts[i] + 1 : 0;
    sm[threadIdx.x] = v;
    __syncthreads();
    for (int o = 128; o; o >>= 1) {
        if (threadIdx.x < o) sm[threadIdx.x] += sm[threadIdx.x + o];
        __syncthreads();
    }
    if (threadIdx.x == 0) g_bsum[blockIdx.x] = sm[0];
}
__global__ void scanB_k() {
    __shared__ int sm[256];
    int t = threadIdx.x;
    int v = (t < NBLK) ? g_bsum[t] : 0;
    sm[t] = v;
    __syncthreads();
    for (int o = 1; o < 256; o <<= 1) {
        int u = (t >= o) ? sm[t - o] : 0;
        __syncthreads();
        sm[t] += u;
        __syncthreads();
    }
    g_bsum[t] = sm[t] - v;
}
__global__ void scanC_k() {
    __shared__ int sm[256];
    int t = threadIdx.x;
    int i = blockIdx.x * 256 + t;
    int v = (i < N_NODES) ? g_counts[i] + 1 : 0;
    sm[t] = v;
    __syncthreads();
    for (int o = 1; o < 256; o <<= 1) {
        int u = (t >= o) ? sm[t - o] : 0;
        __syncthreads();
        sm[t] += u;
        __syncthreads();
    }
    if (i < N_NODES) {
        int off = g_bsum[blockIdx.x] + sm[t] - v;
        g_rowptr[i] = off;
        g_csr_src[off] = i;
        g_cursor[i] = off + 1;
    }
    if (i == 0) g_rowptr[N_NODES] = E_TOT;
}
__global__ void scatter_k(const int* __restrict__ ei) {
    int q = blockIdx.x * blockDim.x + threadIdx.x;
    if (q * 4 >= N_EDGES) return;
    int4 s4 = *(const int4*)(ei + q * 4);
    int4 d4 = *(const int4*)(ei + N_EDGES + q * 4);
    g_csr_src[atomicAdd(&g_cursor[d4.x], 1)] = s4.x;
    g_csr_src[atomicAdd(&g_cursor[d4.y], 1)] = s4.y;
    g_csr_src[atomicAdd(&g_cursor[d4.z], 1)] = s4.z;
    g_csr_src[atomicAdd(&g_cursor[d4.w], 1)] = s4.w;
}

// ---------------- prep kernels ---------------------------------------------------
__global__ void transpose_h_k(const float* __restrict__ W, __half* __restrict__ Bt, int K) {
    int idx = blockIdx.x * blockDim.x + threadIdx.x;
    if (idx >= 256 * K) return;
    int n = idx / K, k = idx - n * K;
    Bt[idx] = __float2half_rn(W[k * 256 + n]);
}
__global__ void transpose2_h_k(const float* __restrict__ W2, __half* __restrict__ Bt2,
                               const float* __restrict__ W3, __half* __restrict__ Bt3) {
    int idx = blockIdx.x * blockDim.x + threadIdx.x;
    const float* W = W2;
    __half* Bt = Bt2;
    if (idx >= 256 * 256) { idx -= 256 * 256; W = W3; Bt = Bt3; }
    int n = idx >> 8, k = idx & 255;
    Bt[idx] = __float2half_rn(W[k * 256 + n]);
}
__global__ void tohalf_k(const float* __restrict__ in, __half* __restrict__ o, int n) {
    int i = blockIdx.x * blockDim.x + threadIdx.x;
    if (i < n) o[i] = __float2half_rn(in[i]);
}

// ---------------- 3-stage cp.async fp16 GEMM, tile 128x256, ldmatrix -------------
// 256 threads, 2x4 warp grid, warp tile 64x64 (one head per warp column band).
#define SMS_H 40
#define TILE_AH (128 * SMS_H)
#define TILE_BH (256 * SMS_H)
#define STAGES 3
#define GEMM_SMEM (STAGES * (TILE_AH + TILE_BH) * 2)   // 92160 B

__global__ __launch_bounds__(256, 1) void gemm_mma(
    const __half* __restrict__ A, const __half* __restrict__ Bt,
    __half* __restrict__ C,
    const float* __restrict__ avs, const float* __restrict__ avd,
    int M, int K)
{
    extern __shared__ __half smh[];
    __half* Abuf = smh;
    __half* Bbuf = smh + STAGES * TILE_AH;
    uint32_t sA0 = (uint32_t)__cvta_generic_to_shared(Abuf);
    uint32_t sB0 = (uint32_t)__cvta_generic_to_shared(Bbuf);

    int t = threadIdx.x;
    int lane = t & 31, wid = t >> 5;
    int wm = wid & 1, wn = wid >> 1;
    int g = lane >> 2, tg = lane & 3;
    int row0 = blockIdx.x * 128;

    // ldmatrix per-lane base offsets (in halves, k-offset excluded)
    // A (mf block): groups lanes[0:8)=rows r..r+7 @kb, [8:16)=r+8..r+15 @kb,
    //               [16:24)=r..r+7 @kb+8, [24:32)=r+8..r+15 @kb+8
    uint32_t a_off[4];
#pragma unroll
    for (int mf = 0; mf < 4; mf++) {
        int rowA = wm * 64 + mf * 16 + (lane & 15);
        int colA = ((lane >> 4) << 3);
        a_off[mf] = rowA * SMS_H + colA;
    }
    // B (nfp block covers nf=2nfp,2nfp+1): groups [0:8)=n..n+7 @kb, [8:16)=n..n+7 @kb+8,
    //               [16:24)=n+8..n+15 @kb, [24:32)=n+8..n+15 @kb+8
    uint32_t b_off[4];
#pragma unroll
    for (int nfp = 0; nfp < 4; nfp++) {
        int rowB = wn * 64 + nfp * 16 + (lane & 7) + ((lane >> 4) << 3);
        int colB = (((lane >> 3) & 1) << 3);
        b_off[nfp] = rowB * SMS_H + colB;
    }

    const int nch = K >> 5;

    auto issue = [&](int kc, int stg) {
        int k0 = kc << 5;
        uint32_t sa = sA0 + stg * (TILE_AH * 2);
        uint32_t sb = sB0 + stg * (TILE_BH * 2);
#pragma unroll
        for (int i = 0; i < 2; i++) {
            int idx = t + (i << 8);
            int r = idx >> 2, c8 = (idx & 3) << 3;
            int gr = row0 + r;
            const __half* srcA = A + (size_t)min(gr, M - 1) * K + k0 + c8;
            cpa16(sa + (r * SMS_H + c8) * 2, srcA, gr < M ? 16 : 0);
        }
#pragma unroll
        for (int i = 0; i < 4; i++) {
            int idx = t + (i << 8);
            int r = idx >> 2, c8 = (idx & 3) << 3;
            const __half* srcB = Bt + (size_t)r * K + k0 + c8;
            cpa16(sb + (r * SMS_H + c8) * 2, srcB, 16);
        }
        asm volatile("cp.async.commit_group;" ::: "memory");
    };

    float c[4][8][4] = {};
    issue(0, 0);
    issue(1, 1);

    for (int kc = 0; kc < nch; kc++) {
        int stg = kc % STAGES;
        if (kc + 2 < nch) {
            issue(kc + 2, (kc + 2) % STAGES);
            asm volatile("cp.async.wait_group 2;" ::: "memory");
        } else if (kc + 1 < nch) {
            asm volatile("cp.async.wait_group 1;" ::: "memory");
        } else {
            asm volatile("cp.async.wait_group 0;" ::: "memory");
        }
        __syncthreads();
        uint32_t saS = sA0 + stg * (TILE_AH * 2);
        uint32_t sbS = sB0 + stg * (TILE_BH * 2);
#pragma unroll
        for (int ks = 0; ks < 2; ks++) {
            int kb = ks * 16;
            uint32_t a[4][4], b[8][2];
#pragma unroll
            for (int mf = 0; mf < 4; mf++)
                LDSM_X4(a[mf][0], a[mf][1], a[mf][2], a[mf][3],
                        saS + (a_off[mf] + kb) * 2);
#pragma unroll
            for (int nfp = 0; nfp < 4; nfp++)
                LDSM_X4(b[2 * nfp][0], b[2 * nfp][1], b[2 * nfp + 1][0], b[2 * nfp + 1][1],
                        sbS + (b_off[nfp] + kb) * 2);
#pragma unroll
            for (int mf = 0; mf < 4; mf++)
#pragma unroll
                for (int nf = 0; nf < 8; nf++)
                    asm volatile(
                        "mma.sync.aligned.m16n8k16.row.col.f32.f16.f16.f32 "
                        "{%0,%1,%2,%3}, {%4,%5,%6,%7}, {%8,%9}, {%0,%1,%2,%3};"
                        : "+f"(c[mf][nf][0]), "+f"(c[mf][nf][1]),
                          "+f"(c[mf][nf][2]), "+f"(c[mf][nf][3])
                        : "r"(a[mf][0]), "r"(a[mf][1]), "r"(a[mf][2]), "r"(a[mf][3]),
                          "r"(b[nf][0]), "r"(b[nf][1]));
        }
        __syncthreads();
    }

    int head = wn;
#pragma unroll
    for (int mf = 0; mf < 4; mf++) {
        int r0 = row0 + wm * 64 + mf * 16 + g;
        int r1 = r0 + 8;
        float sv0 = 0.f, sv1 = 0.f, dv0 = 0.f, dv1 = 0.f;
#pragma unroll
        for (int nf = 0; nf < 8; nf++) {
            int col = wn * 64 + nf * 8 + tg * 2;
            float x0 = c[mf][nf][0], x1 = c[mf][nf][1];
            float x2 = c[mf][nf][2], x3 = c[mf][nf][3];
            if (r0 < M)
                *(__half2*)(C + (size_t)r0 * NCOLS + col) = __floats2half2_rn(x0, x1);
            if (r1 < M)
                *(__half2*)(C + (size_t)r1 * NCOLS + col) = __floats2half2_rn(x2, x3);
            float w0 = __ldg(avs + col), w1 = __ldg(avs + col + 1);
            float u0 = __ldg(avd + col), u1 = __ldg(avd + col + 1);
            sv0 += x0 * w0 + x1 * w1;
            sv1 += x2 * w0 + x3 * w1;
            dv0 += x0 * u0 + x1 * u1;
            dv1 += x2 * u0 + x3 * u1;
        }
        sv0 += __shfl_xor_sync(0xffffffffu, sv0, 1);
        sv0 += __shfl_xor_sync(0xffffffffu, sv0, 2);
        sv1 += __shfl_xor_sync(0xffffffffu, sv1, 1);
        sv1 += __shfl_xor_sync(0xffffffffu, sv1, 2);
        dv0 += __shfl_xor_sync(0xffffffffu, dv0, 1);
        dv0 += __shfl_xor_sync(0xffffffffu, dv0, 2);
        dv1 += __shfl_xor_sync(0xffffffffu, dv1, 1);
        dv1 += __shfl_xor_sync(0xffffffffu, dv1, 2);
        if (tg == 0) {
            if (r0 < M) { g_asrc[r0 * 4 + head] = sv0; g_adst[r0 * 4 + head] = dv0; }
            if (r1 < M) { g_asrc[r1 * 4 + head] = sv1; g_adst[r1 * 4 + head] = dv1; }
        }
    }
}

// ---------------- aggregation: one warp per dst, no-max softmax ------------------
__global__ __launch_bounds__(256) void aggr_k(
    const __half* __restrict__ h, const float* __restrict__ bias,
    __half* __restrict__ out_h, float* __restrict__ out_f)
{
    __shared__ float sw[8][128];
    int d    = (blockIdx.x * blockDim.x + threadIdx.x) >> 5;
    int lane = threadIdx.x & 31;
    int wblk = threadIdx.x >> 5;
    if (d >= N_NODES) return;
    int hol = lane >> 3;
    float* swp = sw[wblk];

    int beg = g_rowptr[d];
    int end = g_rowptr[d + 1];
    float4 adst4 = *(const float4*)(g_adst + d * 4);

    float wsum = 0.f;
    float4 acc0 = make_float4(0.f, 0.f, 0.f, 0.f);
    float4 acc1 = make_float4(0.f, 0.f, 0.f, 0.f);

    for (int base = beg; base < end; base += 32) {
        int i = base + lane;
        bool v = i < end;
        int s_l = v ? g_csr_src[i] : 0;
        float4 w4 = make_float4(0.f, 0.f, 0.f, 0.f);
        if (v) {
            float4 as4 = *(const float4*)(g_asrc + s_l * 4);
            float ex = as4.x + adst4.x, ey = as4.y + adst4.y;
            float ez = as4.z + adst4.z, ew = as4.w + adst4.w;
            ex = ex > 0.f ? ex : SLOPE * ex;
            ey = ey > 0.f ? ey : SLOPE * ey;
            ez = ez > 0.f ? ez : SLOPE * ez;
            ew = ew > 0.f ? ew : SLOPE * ew;
            w4.x = __expf(ex); w4.y = __expf(ey);
            w4.z = __expf(ez); w4.w = __expf(ew);
        }
        *(float4*)(swp + lane * 4) = w4;
        __syncwarp();

        int n = min(32, end - base);
        int j = 0;
        for (; j + 4 <= n; j += 4) {
            int s0 = __shfl_sync(0xffffffffu, s_l, j);
            int s1 = __shfl_sync(0xffffffffu, s_l, j + 1);
            int s2 = __shfl_sync(0xffffffffu, s_l, j + 2);
            int s3 = __shfl_sync(0xffffffffu, s_l, j + 3);
            float w0 = swp[j * 4 + hol];
            float w1 = swp[j * 4 + 4 + hol];
            float w2 = swp[j * 4 + 8 + hol];
            float w3 = swp[j * 4 + 12 + hol];
            wsum += (w0 + w1) + (w2 + w3);
            uint4 v0 = *(const uint4*)(h + (size_t)s0 * NCOLS + lane * 8);
            uint4 v1 = *(const uint4*)(h + (size_t)s1 * NCOLS + lane * 8);
            uint4 v2 = *(const uint4*)(h + (size_t)s2 * NCOLS + lane * 8);
            uint4 v3 = *(const uint4*)(h + (size_t)s3 * NCOLS + lane * 8);
            const __half2* p0 = (const __half2*)&v0;
            const __half2* p1 = (const __half2*)&v1;
            const __half2* p2 = (const __half2*)&v2;
            const __half2* p3 = (const __half2*)&v3;
#pragma unroll
            for (int q = 0; q < 2; q++) {
                float2 f0 = __half22float2(p0[q]), f0b = __half22float2(p0[q + 2]);
                float2 f1 = __half22float2(p1[q]), f1b = __half22float2(p1[q + 2]);
                float2 f2 = __half22float2(p2[q]), f2b = __half22float2(p2[q + 2]);
                float2 f3 = __half22float2(p3[q]), f3b = __half22float2(p3[q + 2]);
                float* a0 = (q == 0) ? &acc0.x : &acc0.z;
                float* a1 = (q == 0) ? &acc1.x : &acc1.z;
                a0[0] += w0 * f0.x + w1 * f1.x + w2 * f2.x + w3 * f3.x;
                a0[1] += w0 * f0.y + w1 * f1.y + w2 * f2.y + w3 * f3.y;
                a1[0] += w0 * f0b.x + w1 * f1b.x + w2 * f2b.x + w3 * f3b.x;
                a1[1] += w0 * f0b.y + w1 * f1b.y + w2 * f2b.y + w3 * f3b.y;
            }
        }
        for (; j < n; j++) {
            int s0 = __shfl_sync(0xffffffffu, s_l, j);
            float w0 = swp[j * 4 + hol];
            wsum += w0;
            uint4 v0 = *(const uint4*)(h + (size_t)s0 * NCOLS + lane * 8);
            const __half2* p0 = (const __half2*)&v0;
            float2 f0 = __half22float2(p0[0]);
            float2 f1 = __half22float2(p0[1]);
            float2 f2 = __half22float2(p0[2]);
            float2 f3 = __half22float2(p0[3]);
            acc0.x += w0 * f0.x; acc0.y += w0 * f0.y;
            acc0.z += w0 * f1.x; acc0.w += w0 * f1.y;
            acc1.x += w0 * f2.x; acc1.y += w0 * f2.y;
            acc1.z += w0 * f3.x; acc1.w += w0 * f3.y;
        }
        __syncwarp();
    }

    float inv = 1.f / wsum;
    int c0 = lane * 8;
    float4 bb0 = *(const float4*)(bias + c0);
    float4 bb1 = *(const float4*)(bias + c0 + 4);
    float o_[8];
    o_[0] = acc0.x * inv + bb0.x; o_[1] = acc0.y * inv + bb0.y;
    o_[2] = acc0.z * inv + bb0.z; o_[3] = acc0.w * inv + bb0.w;
    o_[4] = acc1.x * inv + bb1.x; o_[5] = acc1.y * inv + bb1.y;
    o_[6] = acc1.z * inv + bb1.z; o_[7] = acc1.w * inv + bb1.w;
#pragma unroll
    for (int k = 0; k < 8; k++) {
        float o = o_[k];
        o_[k] = o > 0.f ? o : (__expf(o) - 1.f);
    }
    if (out_h) {
        __half2 hh[4];
        hh[0] = __floats2half2_rn(o_[0], o_[1]);
        hh[1] = __floats2half2_rn(o_[2], o_[3]);
        hh[2] = __floats2half2_rn(o_[4], o_[5]);
        hh[3] = __floats2half2_rn(o_[6], o_[7]);
        *(uint4*)(out_h + (size_t)d * NCOLS + c0) = *(uint4*)hh;
    } else {
        *(float4*)(out_f + (size_t)d * NCOLS + c0)     = make_float4(o_[0], o_[1], o_[2], o_[3]);
        *(float4*)(out_f + (size_t)d * NCOLS + c0 + 4) = make_float4(o_[4], o_[5], o_[6], o_[7]);
    }
}

// ---------------- driver ---------------------------------------------------------
extern "C" void kernel_launch(void* const* d_in, const int* in_sizes, int n_in,
                              void* d_out, int out_size)
{
    const float* inp = (const float*)d_in[0];
    const int*   ei  = (const int*)d_in[1];
    const float* W1  = (const float*)d_in[2];
    const float* as1 = (const float*)d_in[3];
    const float* ad1 = (const float*)d_in[4];
    const float* b1  = (const float*)d_in[5];
    const float* W2  = (const float*)d_in[6];
    const float* as2 = (const float*)d_in[7];
    const float* ad2 = (const float*)d_in[8];
    const float* b2  = (const float*)d_in[9];
    const float* W3  = (const float*)d_in[10];
    const float* as3 = (const float*)d_in[11];
    const float* ad3 = (const float*)d_in[12];
    const float* b3  = (const float*)d_in[13];
    float* out = (float*)d_out;

    __half *hbuf, *xh, *bt1, *bt2, *bt3;
    int* counts;
    cudaGetSymbolAddress((void**)&hbuf, g_h);
    cudaGetSymbolAddress((void**)&xh, g_xh);
    cudaGetSymbolAddress((void**)&bt1, g_bt1);
    cudaGetSymbolAddress((void**)&bt2, g_bt2);
    cudaGetSymbolAddress((void**)&bt3, g_bt3);
    cudaGetSymbolAddress((void**)&counts, g_counts);

    cudaFuncSetAttribute(gemm_mma, cudaFuncAttributeMaxDynamicSharedMemorySize, GEMM_SMEM);

    static cudaStream_t s2 = nullptr;
    static cudaEvent_t e_fork = nullptr, e_join = nullptr;
    if (!s2) {
        cudaStreamCreateWithFlags(&s2, cudaStreamNonBlocking);
        cudaEventCreateWithFlags(&e_fork, cudaEventDisableTiming);
        cudaEventCreateWithFlags(&e_join, cudaEventDisableTiming);
    }

    int ggrid = (N_NODES + 127) / 128;
    int agrid = (N_NODES * 32 + 255) / 256;

    cudaEventRecord(e_fork, 0);

    // main stream: layer-1 prep + GEMM (kernel #4 = gemm -> ncu capture)
    transpose_h_k<<<(256 * 128 + 255) / 256, 256>>>(W1, bt1, 128);
    tohalf_k<<<(N_NODES * 128 + 255) / 256, 256>>>(inp, xh, N_NODES * 128);
    transpose2_h_k<<<(2 * 256 * 256 + 255) / 256, 256>>>(W2, bt2, W3, bt3);
    gemm_mma<<<ggrid, 256, GEMM_SMEM>>>(xh, bt1, hbuf, as1, ad1, N_NODES, 128);

    // fork stream: CSR build (only gates aggr1)
    cudaStreamWaitEvent(s2, e_fork, 0);
    cudaMemsetAsync(counts, 0, N_NODES * sizeof(int), s2);
    hist_k<<<(N_EDGES / 4 + 255) / 256, 256, 0, s2>>>(ei);
    scanA_k<<<NBLK, 256, 0, s2>>>();
    scanB_k<<<1, 256, 0, s2>>>();
    scanC_k<<<NBLK, 256, 0, s2>>>();
    scatter_k<<<(N_EDGES / 4 + 255) / 256, 256, 0, s2>>>(ei);
    cudaEventRecord(e_join, s2);

    cudaStreamWaitEvent(0, e_join, 0);
    aggr_k<<<agrid, 256>>>(hbuf, b1, xh, nullptr);

    gemm_mma<<<ggrid, 256, GEMM_SMEM>>>(xh, bt2, hbuf, as2, ad2, N_NODES, 256);
    aggr_k<<<agrid, 256>>>(hbuf, b2, xh, nullptr);

    gemm_mma<<<ggrid, 256, GEMM_SMEM>>>(xh, bt3, hbuf, as3, ad3, N_NODES, 256);
    aggr_k<<<agrid, 256>>>(hbuf, b3, nullptr, out);
}

// round 13
// speedup vs baseline: 1.0149x; 1.0025x over previous
#include <cuda_runtime.h>
#include <cuda_fp16.h>
#include <cstdint>

#define N_NODES 50000
#define N_EDGES 800000
#define E_TOT   (N_EDGES + N_NODES)
#define NCOLS   256
#define SLOPE   0.2f
#define NBLK    ((N_NODES + 255) / 256)
#define NTILES  ((N_NODES + 127) / 128)   // 391
#define PGRID   152                        // persistent CTAs (GB300: 152 SMs)

// ---------------- scratch (device globals) -----------------------------------
__device__ __half g_h[N_NODES * NCOLS];
__device__ __half g_xh[N_NODES * NCOLS];
__device__ __half g_bt1[256 * 128];
__device__ __half g_bt2[256 * 256];
__device__ __half g_bt3[256 * 256];
__device__ float  g_asrc[N_NODES * 4];
__device__ float  g_adst[N_NODES * 4];
__device__ int    g_counts[N_NODES];
__device__ int    g_bsum[256];
__device__ int    g_rowptr[N_NODES + 1];
__device__ int    g_cursor[N_NODES];
__device__ int    g_csr_src[E_TOT];

__device__ __forceinline__ void cpa16(uint32_t sdst, const void* gsrc, int srcsize) {
    asm volatile("cp.async.cg.shared.global [%0], [%1], 16, %2;"
                 :: "r"(sdst), "l"(gsrc), "r"(srcsize));
}
#define LDSM_X4(r0, r1, r2, r3, addr) \
    asm volatile("ldmatrix.sync.aligned.m8n8.x4.shared.b16 {%0,%1,%2,%3}, [%4];" \
                 : "=r"(r0), "=r"(r1), "=r"(r2), "=r"(r3) : "r"(addr))

// ---------------- CSR build (fast path) ------------------------------------------
__global__ void hist_k(const int* __restrict__ ei) {
    int q = blockIdx.x * blockDim.x + threadIdx.x;
    if (q * 4 >= N_EDGES) return;
    int4 d4 = *(const int4*)(ei + N_EDGES + q * 4);
    atomicAdd(&g_counts[d4.x], 1);
    atomicAdd(&g_counts[d4.y], 1);
    atomicAdd(&g_counts[d4.z], 1);
    atomicAdd(&g_counts[d4.w], 1);
}
__global__ void scanA_k() {
    __shared__ int sm[256];
    int i = blockIdx.x * 256 + threadIdx.x;
    int v = (i < N_NODES) ? g_counts[i] + 1 : 0;
    sm[threadIdx.x] = v;
    __syncthreads();
    for (int o = 128; o; o >>= 1) {
        if (threadIdx.x < o) sm[threadIdx.x] += sm[threadIdx.x + o];
        __syncthreads();
    }
    if (threadIdx.x == 0) g_bsum[blockIdx.x] = sm[0];
}
__global__ void scanB_k() {
    __shared__ int sm[256];
    int t = threadIdx.x;
    int v = (t < NBLK) ? g_bsum[t] : 0;
    sm[t] = v;
    __syncthreads();
    for (int o = 1; o < 256; o <<= 1) {
        int u = (t >= o) ? sm[t - o] : 0;
        __syncthreads();
        sm[t] += u;
        __syncthreads();
    }
    g_bsum[t] = sm[t] - v;
}
__global__ void scanC_k() {
    __shared__ int sm[256];
    int t = threadIdx.x;
    int i = blockIdx.x * 256 + t;
    int v = (i < N_NODES) ? g_counts[i] + 1 : 0;
    sm[t] = v;
    __syncthreads();
    for (int o = 1; o < 256; o <<= 1) {
        int u = (t >= o) ? sm[t - o] : 0;
        __syncthreads();
        sm[t] += u;
        __syncthreads();
    }
    if (i < N_NODES) {
        int off = g_bsum[blockIdx.x] + sm[t] - v;
        g_rowptr[i] = off;
        g_csr_src[off] = i;
        g_cursor[i] = off + 1;
    }
    if (i == 0) g_rowptr[N_NODES] = E_TOT;
}
__global__ void scatter_k(const int* __restrict__ ei) {
    int q = blockIdx.x * blockDim.x + threadIdx.x;
    if (q * 4 >= N_EDGES) return;
    int4 s4 = *(const int4*)(ei + q * 4);
    int4 d4 = *(const int4*)(ei + N_EDGES + q * 4);
    g_csr_src[atomicAdd(&g_cursor[d4.x], 1)] = s4.x;
    g_csr_src[atomicAdd(&g_cursor[d4.y], 1)] = s4.y;
    g_csr_src[atomicAdd(&g_cursor[d4.z], 1)] = s4.z;
    g_csr_src[atomicAdd(&g_cursor[d4.w], 1)] = s4.w;
}

// ---------------- prep kernels ---------------------------------------------------
__global__ void transpose_h_k(const float* __restrict__ W, __half* __restrict__ Bt, int K) {
    int idx = blockIdx.x * blockDim.x + threadIdx.x;
    if (idx >= 256 * K) return;
    int n = idx / K, k = idx - n * K;
    Bt[idx] = __float2half_rn(W[k * 256 + n]);
}
__global__ void transpose2_h_k(const float* __restrict__ W2, __half* __restrict__ Bt2,
                               const float* __restrict__ W3, __half* __restrict__ Bt3) {
    int idx = blockIdx.x * blockDim.x + threadIdx.x;
    const float* W = W2;
    __half* Bt = Bt2;
    if (idx >= 256 * 256) { idx -= 256 * 256; W = W3; Bt = Bt3; }
    int n = idx >> 8, k = idx & 255;
    Bt[idx] = __float2half_rn(W[k * 256 + n]);
}
__global__ void tohalf_k(const float* __restrict__ in, __half* __restrict__ o, int n) {
    int i = blockIdx.x * blockDim.x + threadIdx.x;
    if (i < n) o[i] = __float2half_rn(in[i]);
}

// ---------------- persistent 3-stage cp.async fp16 GEMM --------------------------
// grid=PGRID; each CTA loops over row tiles with a continuous chunk pipeline.
#define SMS_H 40
#define TILE_AH (128 * SMS_H)
#define TILE_BH (256 * SMS_H)
#define STAGES 3
#define GEMM_SMEM (STAGES * (TILE_AH + TILE_BH) * 2)   // 92160 B

__global__ __launch_bounds__(256, 1) void gemm_mma(
    const __half* __restrict__ A, const __half* __restrict__ Bt,
    __half* __restrict__ C,
    const float* __restrict__ avs, const float* __restrict__ avd,
    int M, int K)
{
    extern __shared__ __half smh[];
    __half* Abuf = smh;
    __half* Bbuf = smh + STAGES * TILE_AH;
    uint32_t sA0 = (uint32_t)__cvta_generic_to_shared(Abuf);
    uint32_t sB0 = (uint32_t)__cvta_generic_to_shared(Bbuf);

    int t = threadIdx.x;
    int lane = t & 31, wid = t >> 5;
    int wm = wid & 1, wn = wid >> 1;
    int g = lane >> 2, tg = lane & 3;

    const int lg = (K == 128) ? 2 : 3;     // log2(nch)
    const int nch = 1 << lg;
    const int ntiles = (M + 127) >> 7;
    const int nt = (ntiles - blockIdx.x + gridDim.x - 1) / gridDim.x;
    if (nt == 0) return;
    const int total = nt << lg;

    // ldmatrix per-lane base offsets (in halves)
    uint32_t a_off[4];
#pragma unroll
    for (int mf = 0; mf < 4; mf++) {
        int rowA = wm * 64 + mf * 16 + (lane & 15);
        int colA = ((lane >> 4) << 3);
        a_off[mf] = rowA * SMS_H + colA;
    }
    uint32_t b_off[4];
#pragma unroll
    for (int nfp = 0; nfp < 4; nfp++) {
        int rowB = wn * 64 + nfp * 16 + (lane & 7) + ((lane >> 4) << 3);
        int colB = (((lane >> 3) & 1) << 3);
        b_off[nfp] = rowB * SMS_H + colB;
    }

    auto issue = [&](int l) {
        int i = l >> lg, kc = l & (nch - 1);
        int row0 = (blockIdx.x + i * gridDim.x) << 7;
        int stg = l % STAGES;
        int k0 = kc << 5;
        uint32_t sa = sA0 + stg * (TILE_AH * 2);
        uint32_t sb = sB0 + stg * (TILE_BH * 2);
#pragma unroll
        for (int q = 0; q < 2; q++) {
            int idx = t + (q << 8);
            int r = idx >> 2, c8 = (idx & 3) << 3;
            int gr = row0 + r;
            const __half* srcA = A + (size_t)min(gr, M - 1) * K + k0 + c8;
            cpa16(sa + (r * SMS_H + c8) * 2, srcA, gr < M ? 16 : 0);
        }
#pragma unroll
        for (int q = 0; q < 4; q++) {
            int idx = t + (q << 8);
            int r = idx >> 2, c8 = (idx & 3) << 3;
            const __half* srcB = Bt + (size_t)r * K + k0 + c8;
            cpa16(sb + (r * SMS_H + c8) * 2, srcB, 16);
        }
        asm volatile("cp.async.commit_group;" ::: "memory");
    };

    float c[4][8][4] = {};
    issue(0);
    if (total > 1) issue(1);

    for (int l = 0; l < total; l++) {
        if (l + 2 < total) {
            issue(l + 2);
            asm volatile("cp.async.wait_group 2;" ::: "memory");
        } else if (l + 1 < total) {
            asm volatile("cp.async.wait_group 1;" ::: "memory");
        } else {
            asm volatile("cp.async.wait_group 0;" ::: "memory");
        }
        __syncthreads();
        int stg = l % STAGES;
        uint32_t saS = sA0 + stg * (TILE_AH * 2);
        uint32_t sbS = sB0 + stg * (TILE_BH * 2);
#pragma unroll
        for (int ks = 0; ks < 2; ks++) {
            int kb = ks * 16;
            uint32_t a[4][4], b[8][2];
#pragma unroll
            for (int mf = 0; mf < 4; mf++)
                LDSM_X4(a[mf][0], a[mf][1], a[mf][2], a[mf][3],
                        saS + (a_off[mf] + kb) * 2);
#pragma unroll
            for (int nfp = 0; nfp < 4; nfp++)
                LDSM_X4(b[2 * nfp][0], b[2 * nfp][1], b[2 * nfp + 1][0], b[2 * nfp + 1][1],
                        sbS + (b_off[nfp] + kb) * 2);
#pragma unroll
            for (int mf = 0; mf < 4; mf++)
#pragma unroll
                for (int nf = 0; nf < 8; nf++)
                    asm volatile(
                        "mma.sync.aligned.m16n8k16.row.col.f32.f16.f16.f32 "
                        "{%0,%1,%2,%3}, {%4,%5,%6,%7}, {%8,%9}, {%0,%1,%2,%3};"
                        : "+f"(c[mf][nf][0]), "+f"(c[mf][nf][1]),
                          "+f"(c[mf][nf][2]), "+f"(c[mf][nf][3])
                        : "r"(a[mf][0]), "r"(a[mf][1]), "r"(a[mf][2]), "r"(a[mf][3]),
                          "r"(b[nf][0]), "r"(b[nf][1]));
        }
        __syncthreads();

        if ((l & (nch - 1)) == nch - 1) {
            // epilogue for finished tile (registers + global only; pipeline continues)
            int row0 = (blockIdx.x + (l >> lg) * gridDim.x) << 7;
            int head = wn;
#pragma unroll
            for (int mf = 0; mf < 4; mf++) {
                int r0 = row0 + wm * 64 + mf * 16 + g;
                int r1 = r0 + 8;
                float sv0 = 0.f, sv1 = 0.f, dv0 = 0.f, dv1 = 0.f;
#pragma unroll
                for (int nf = 0; nf < 8; nf++) {
                    int col = wn * 64 + nf * 8 + tg * 2;
                    float x0 = c[mf][nf][0], x1 = c[mf][nf][1];
                    float x2 = c[mf][nf][2], x3 = c[mf][nf][3];
                    if (r0 < M)
                        *(__half2*)(C + (size_t)r0 * NCOLS + col) = __floats2half2_rn(x0, x1);
                    if (r1 < M)
                        *(__half2*)(C + (size_t)r1 * NCOLS + col) = __floats2half2_rn(x2, x3);
                    float w0 = __ldg(avs + col), w1 = __ldg(avs + col + 1);
                    float u0 = __ldg(avd + col), u1 = __ldg(avd + col + 1);
                    sv0 += x0 * w0 + x1 * w1;
                    sv1 += x2 * w0 + x3 * w1;
                    dv0 += x0 * u0 + x1 * u1;
                    dv1 += x2 * u0 + x3 * u1;
                }
                sv0 += __shfl_xor_sync(0xffffffffu, sv0, 1);
                sv0 += __shfl_xor_sync(0xffffffffu, sv0, 2);
                sv1 += __shfl_xor_sync(0xffffffffu, sv1, 1);
                sv1 += __shfl_xor_sync(0xffffffffu, sv1, 2);
                dv0 += __shfl_xor_sync(0xffffffffu, dv0, 1);
                dv0 += __shfl_xor_sync(0xffffffffu, dv0, 2);
                dv1 += __shfl_xor_sync(0xffffffffu, dv1, 1);
                dv1 += __shfl_xor_sync(0xffffffffu, dv1, 2);
                if (tg == 0) {
                    if (r0 < M) { g_asrc[r0 * 4 + head] = sv0; g_adst[r0 * 4 + head] = dv0; }
                    if (r1 < M) { g_asrc[r1 * 4 + head] = sv1; g_adst[r1 * 4 + head] = dv1; }
                }
            }
            // reset accumulators for next tile
#pragma unroll
            for (int mf = 0; mf < 4; mf++)
#pragma unroll
                for (int nf = 0; nf < 8; nf++) {
                    c[mf][nf][0] = 0.f; c[mf][nf][1] = 0.f;
                    c[mf][nf][2] = 0.f; c[mf][nf][3] = 0.f;
                }
        }
    }
}

// ---------------- aggregation: one warp per dst, no-max softmax ------------------
__global__ __launch_bounds__(256) void aggr_k(
    const __half* __restrict__ h, const float* __restrict__ bias,
    __half* __restrict__ out_h, float* __restrict__ out_f)
{
    __shared__ float sw[8][128];
    int d    = (blockIdx.x * blockDim.x + threadIdx.x) >> 5;
    int lane = threadIdx.x & 31;
    int wblk = threadIdx.x >> 5;
    if (d >= N_NODES) return;
    int hol = lane >> 3;
    float* swp = sw[wblk];

    int beg = g_rowptr[d];
    int end = g_rowptr[d + 1];
    float4 adst4 = *(const float4*)(g_adst + d * 4);

    float wsum = 0.f;
    float4 acc0 = make_float4(0.f, 0.f, 0.f, 0.f);
    float4 acc1 = make_float4(0.f, 0.f, 0.f, 0.f);

    for (int base = beg; base < end; base += 32) {
        int i = base + lane;
        bool v = i < end;
        int s_l = v ? g_csr_src[i] : 0;
        float4 w4 = make_float4(0.f, 0.f, 0.f, 0.f);
        if (v) {
            float4 as4 = *(const float4*)(g_asrc + s_l * 4);
            float ex = as4.x + adst4.x, ey = as4.y + adst4.y;
            float ez = as4.z + adst4.z, ew = as4.w + adst4.w;
            ex = ex > 0.f ? ex : SLOPE * ex;
            ey = ey > 0.f ? ey : SLOPE * ey;
            ez = ez > 0.f ? ez : SLOPE * ez;
            ew = ew > 0.f ? ew : SLOPE * ew;
            w4.x = __expf(ex); w4.y = __expf(ey);
            w4.z = __expf(ez); w4.w = __expf(ew);
        }
        *(float4*)(swp + lane * 4) = w4;
        __syncwarp();

        int n = min(32, end - base);
        int j = 0;
        for (; j + 4 <= n; j += 4) {
            int s0 = __shfl_sync(0xffffffffu, s_l, j);
            int s1 = __shfl_sync(0xffffffffu, s_l, j + 1);
            int s2 = __shfl_sync(0xffffffffu, s_l, j + 2);
            int s3 = __shfl_sync(0xffffffffu, s_l, j + 3);
            float w0 = swp[j * 4 + hol];
            float w1 = swp[j * 4 + 4 + hol];
            float w2 = swp[j * 4 + 8 + hol];
            float w3 = swp[j * 4 + 12 + hol];
            wsum += (w0 + w1) + (w2 + w3);
            uint4 v0 = *(const uint4*)(h + (size_t)s0 * NCOLS + lane * 8);
            uint4 v1 = *(const uint4*)(h + (size_t)s1 * NCOLS + lane * 8);
            uint4 v2 = *(const uint4*)(h + (size_t)s2 * NCOLS + lane * 8);
            uint4 v3 = *(const uint4*)(h + (size_t)s3 * NCOLS + lane * 8);
            const __half2* p0 = (const __half2*)&v0;
            const __half2* p1 = (const __half2*)&v1;
            const __half2* p2 = (const __half2*)&v2;
            const __half2* p3 = (const __half2*)&v3;
#pragma unroll
            for (int q = 0; q < 2; q++) {
                float2 f0 = __half22float2(p0[q]), f0b = __half22float2(p0[q + 2]);
                float2 f1 = __half22float2(p1[q]), f1b = __half22float2(p1[q + 2]);
                float2 f2 = __half22float2(p2[q]), f2b = __half22float2(p2[q + 2]);
                float2 f3 = __half22float2(p3[q]), f3b = __half22float2(p3[q + 2]);
                float* a0 = (q == 0) ? &acc0.x : &acc0.z;
                float* a1 = (q == 0) ? &acc1.x : &acc1.z;
                a0[0] += w0 * f0.x + w1 * f1.x + w2 * f2.x + w3 * f3.x;
                a0[1] += w0 * f0.y + w1 * f1.y + w2 * f2.y + w3 * f3.y;
                a1[0] += w0 * f0b.x + w1 * f1b.x + w2 * f2b.x + w3 * f3b.x;
                a1[1] += w0 * f0b.y + w1 * f1b.y + w2 * f2b.y + w3 * f3b.y;
            }
        }
        for (; j < n; j++) {
            int s0 = __shfl_sync(0xffffffffu, s_l, j);
            float w0 = swp[j * 4 + hol];
            wsum += w0;
            uint4 v0 = *(const uint4*)(h + (size_t)s0 * NCOLS + lane * 8);
            const __half2* p0 = (const __half2*)&v0;
            float2 f0 = __half22float2(p0[0]);
            float2 f1 = __half22float2(p0[1]);
            float2 f2 = __half22float2(p0[2]);
            float2 f3 = __half22float2(p0[3]);
            acc0.x += w0 * f0.x; acc0.y += w0 * f0.y;
            acc0.z += w0 * f1.x; acc0.w += w0 * f1.y;
            acc1.x += w0 * f2.x; acc1.y += w0 * f2.y;
            acc1.z += w0 * f3.x; acc1.w += w0 * f3.y;
        }
        __syncwarp();
    }

    float inv = 1.f / wsum;
    int c0 = lane * 8;
    float4 bb0 = *(const float4*)(bias + c0);
    float4 bb1 = *(const float4*)(bias + c0 + 4);
    float o_[8];
    o_[0] = acc0.x * inv + bb0.x; o_[1] = acc0.y * inv + bb0.y;
    o_[2] = acc0.z * inv + bb0.z; o_[3] = acc0.w * inv + bb0.w;
    o_[4] = acc1.x * inv + bb1.x; o_[5] = acc1.y * inv + bb1.y;
    o_[6] = acc1.z * inv + bb1.z; o_[7] = acc1.w * inv + bb1.w;
#pragma unroll
    for (int k = 0; k < 8; k++) {
        float o = o_[k];
        o_[k] = o > 0.f ? o : (__expf(o) - 1.f);
    }
    if (out_h) {
        __half2 hh[4];
        hh[0] = __floats2half2_rn(o_[0], o_[1]);
        hh[1] = __floats2half2_rn(o_[2], o_[3]);
        hh[2] = __floats2half2_rn(o_[4], o_[5]);
        hh[3] = __floats2half2_rn(o_[6], o_[7]);
        *(uint4*)(out_h + (size_t)d * NCOLS + c0) = *(uint4*)hh;
    } else {
        *(float4*)(out_f + (size_t)d * NCOLS + c0)     = make_float4(o_[0], o_[1], o_[2], o_[3]);
        *(float4*)(out_f + (size_t)d * NCOLS + c0 + 4) = make_float4(o_[4], o_[5], o_[6], o_[7]);
    }
}

// ---------------- driver ---------------------------------------------------------
extern "C" void kernel_launch(void* const* d_in, const int* in_sizes, int n_in,
                              void* d_out, int out_size)
{
    const float* inp = (const float*)d_in[0];
    const int*   ei  = (const int*)d_in[1];
    const float* W1  = (const float*)d_in[2];
    const float* as1 = (const float*)d_in[3];
    const float* ad1 = (const float*)d_in[4];
    const float* b1  = (const float*)d_in[5];
    const float* W2  = (const float*)d_in[6];
    const float* as2 = (const float*)d_in[7];
    const float* ad2 = (const float*)d_in[8];
    const float* b2  = (const float*)d_in[9];
    const float* W3  = (const float*)d_in[10];
    const float* as3 = (const float*)d_in[11];
    const float* ad3 = (const float*)d_in[12];
    const float* b3  = (const float*)d_in[13];
    float* out = (float*)d_out;

    __half *hbuf, *xh, *bt1, *bt2, *bt3;
    int* counts;
    cudaGetSymbolAddress((void**)&hbuf, g_h);
    cudaGetSymbolAddress((void**)&xh, g_xh);
    cudaGetSymbolAddress((void**)&bt1, g_bt1);
    cudaGetSymbolAddress((void**)&bt2, g_bt2);
    cudaGetSymbolAddress((void**)&bt3, g_bt3);
    cudaGetSymbolAddress((void**)&counts, g_counts);

    cudaFuncSetAttribute(gemm_mma, cudaFuncAttributeMaxDynamicSharedMemorySize, GEMM_SMEM);

    static cudaStream_t s2 = nullptr;
    static cudaEvent_t e_fork = nullptr, e_join = nullptr;
    if (!s2) {
        cudaStreamCreateWithFlags(&s2, cudaStreamNonBlocking);
        cudaEventCreateWithFlags(&e_fork, cudaEventDisableTiming);
        cudaEventCreateWithFlags(&e_join, cudaEventDisableTiming);
    }

    int ggrid = PGRID;
    int agrid = (N_NODES * 32 + 255) / 256;

    cudaEventRecord(e_fork, 0);

    // main stream: layer-1 prep + GEMM (kernel #4 = gemm -> ncu capture)
    transpose_h_k<<<(256 * 128 + 255) / 256, 256>>>(W1, bt1, 128);
    tohalf_k<<<(N_NODES * 128 + 255) / 256, 256>>>(inp, xh, N_NODES * 128);
    transpose2_h_k<<<(2 * 256 * 256 + 255) / 256, 256>>>(W2, bt2, W3, bt3);
    gemm_mma<<<ggrid, 256, GEMM_SMEM>>>(xh, bt1, hbuf, as1, ad1, N_NODES, 128);

    // fork stream: CSR build (only gates aggr1)
    cudaStreamWaitEvent(s2, e_fork, 0);
    cudaMemsetAsync(counts, 0, N_NODES * sizeof(int), s2);
    hist_k<<<(N_EDGES / 4 + 255) / 256, 256, 0, s2>>>(ei);
    scanA_k<<<NBLK, 256, 0, s2>>>();
    scanB_k<<<1, 256, 0, s2>>>();
    scanC_k<<<NBLK, 256, 0, s2>>>();
    scatter_k<<<(N_EDGES / 4 + 255) / 256, 256, 0, s2>>>(ei);
    cudaEventRecord(e_join, s2);

    cudaStreamWaitEvent(0, e_join, 0);
    aggr_k<<<agrid, 256>>>(hbuf, b1, xh, nullptr);

    gemm_mma<<<ggrid, 256, GEMM_SMEM>>>(xh, bt2, hbuf, as2, ad2, N_NODES, 256);
    aggr_k<<<agrid, 256>>>(hbuf, b2, xh, nullptr);

    gemm_mma<<<ggrid, 256, GEMM_SMEM>>>(xh, bt3, hbuf, as3, ad3, N_NODES, 256);
    aggr_k<<<agrid, 256>>>(hbuf, b3, nullptr, out);
}

// round 14
// speedup vs baseline: 1.0200x; 1.0051x over previous
#include <cuda_runtime.h>
#include <cuda_fp16.h>
#include <cstdint>

#define N_NODES 50000
#define N_EDGES 800000
#define E_TOT   (N_EDGES + N_NODES)
#define NCOLS   256
#define SLOPE   0.2f
#define NBLK    ((N_NODES + 255) / 256)

// ---------------- scratch (device globals) -----------------------------------
__device__ __half g_h[N_NODES * NCOLS];
__device__ __half g_xh[N_NODES * NCOLS];
__device__ __half g_bt1[256 * 128];
__device__ __half g_bt2[256 * 256];
__device__ __half g_bt3[256 * 256];
__device__ float  g_asrc[N_NODES * 4];
__device__ float  g_adst[N_NODES * 4];
__device__ int    g_counts[N_NODES];
__device__ int    g_bsum[256];
__device__ int    g_rowptr[N_NODES + 1];
__device__ int    g_cursor[N_NODES];
__device__ int    g_csr_src[E_TOT];

__device__ __forceinline__ void cpa16(uint32_t sdst, const void* gsrc, int srcsize) {
    asm volatile("cp.async.cg.shared.global [%0], [%1], 16, %2;"
                 :: "r"(sdst), "l"(gsrc), "r"(srcsize));
}
#define LDSM_X4(r0, r1, r2, r3, addr) \
    asm volatile("ldmatrix.sync.aligned.m8n8.x4.shared.b16 {%0,%1,%2,%3}, [%4];" \
                 : "=r"(r0), "=r"(r1), "=r"(r2), "=r"(r3) : "r"(addr))

// ---------------- CSR build (fast path) ------------------------------------------
__global__ void hist_k(const int* __restrict__ ei) {
    int q = blockIdx.x * blockDim.x + threadIdx.x;
    if (q * 4 >= N_EDGES) return;
    int4 d4 = *(const int4*)(ei + N_EDGES + q * 4);
    atomicAdd(&g_counts[d4.x], 1);
    atomicAdd(&g_counts[d4.y], 1);
    atomicAdd(&g_counts[d4.z], 1);
    atomicAdd(&g_counts[d4.w], 1);
}
__global__ void scanA_k() {
    __shared__ int sm[256];
    int i = blockIdx.x * 256 + threadIdx.x;
    int v = (i < N_NODES) ? g_counts[i] + 1 : 0;
    sm[threadIdx.x] = v;
    __syncthreads();
    for (int o = 128; o; o >>= 1) {
        if (threadIdx.x < o) sm[threadIdx.x] += sm[threadIdx.x + o];
        __syncthreads();
    }
    if (threadIdx.x == 0) g_bsum[blockIdx.x] = sm[0];
}
__global__ void scanB_k() {
    __shared__ int sm[256];
    int t = threadIdx.x;
    int v = (t < NBLK) ? g_bsum[t] : 0;
    sm[t] = v;
    __syncthreads();
    for (int o = 1; o < 256; o <<= 1) {
        int u = (t >= o) ? sm[t - o] : 0;
        __syncthreads();
        sm[t] += u;
        __syncthreads();
    }
    g_bsum[t] = sm[t] - v;
}
__global__ void scanC_k() {
    __shared__ int sm[256];
    int t = threadIdx.x;
    int i = blockIdx.x * 256 + t;
    int v = (i < N_NODES) ? g_counts[i] + 1 : 0;
    sm[t] = v;
    __syncthreads();
    for (int o = 1; o < 256; o <<= 1) {
        int u = (t >= o) ? sm[t - o] : 0;
        __syncthreads();
        sm[t] += u;
        __syncthreads();
    }
    if (i < N_NODES) {
        int off = g_bsum[blockIdx.x] + sm[t] - v;
        g_rowptr[i] = off;
        g_csr_src[off] = i;
        g_cursor[i] = off + 1;
    }
    if (i == 0) g_rowptr[N_NODES] = E_TOT;
}
__global__ void scatter_k(const int* __restrict__ ei) {
    int q = blockIdx.x * blockDim.x + threadIdx.x;
    if (q * 4 >= N_EDGES) return;
    int4 s4 = *(const int4*)(ei + q * 4);
    int4 d4 = *(const int4*)(ei + N_EDGES + q * 4);
    g_csr_src[atomicAdd(&g_cursor[d4.x], 1)] = s4.x;
    g_csr_src[atomicAdd(&g_cursor[d4.y], 1)] = s4.y;
    g_csr_src[atomicAdd(&g_cursor[d4.z], 1)] = s4.z;
    g_csr_src[atomicAdd(&g_cursor[d4.w], 1)] = s4.w;
}

// ---------------- prep kernels ---------------------------------------------------
__global__ void transpose_h_k(const float* __restrict__ W, __half* __restrict__ Bt, int K) {
    int idx = blockIdx.x * blockDim.x + threadIdx.x;
    if (idx >= 256 * K) return;
    int n = idx / K, k = idx - n * K;
    Bt[idx] = __float2half_rn(W[k * 256 + n]);
}
__global__ void transpose2_h_k(const float* __restrict__ W2, __half* __restrict__ Bt2,
                               const float* __restrict__ W3, __half* __restrict__ Bt3) {
    int idx = blockIdx.x * blockDim.x + threadIdx.x;
    const float* W = W2;
    __half* Bt = Bt2;
    if (idx >= 256 * 256) { idx -= 256 * 256; W = W3; Bt = Bt3; }
    int n = idx >> 8, k = idx & 255;
    Bt[idx] = __float2half_rn(W[k * 256 + n]);
}
__global__ void tohalf_k(const float* __restrict__ in, __half* __restrict__ o, int n) {
    int i = blockIdx.x * blockDim.x + threadIdx.x;
    if (i < n) o[i] = __float2half_rn(in[i]);
}

// ---------------- 3-stage cp.async fp16 GEMM, tile 128x128, 2 CTAs/SM ------------
// 256 threads, 2x4 warp grid, warp tile 64x32 (warp col band within one head).
#define SMS_H 40
#define TILE_AH (128 * SMS_H)
#define TILE_BH (128 * SMS_H)
#define STAGES 3
#define GEMM_SMEM (STAGES * (TILE_AH + TILE_BH) * 2)   // 61440 B -> 2 CTAs/SM

__global__ __launch_bounds__(256, 2) void gemm_mma(
    const __half* __restrict__ A, const __half* __restrict__ Bt,
    __half* __restrict__ C,
    const float* __restrict__ avs, const float* __restrict__ avd,
    int M, int K)
{
    extern __shared__ __half smh[];
    __half* Abuf = smh;
    __half* Bbuf = smh + STAGES * TILE_AH;
    uint32_t sA0 = (uint32_t)__cvta_generic_to_shared(Abuf);
    uint32_t sB0 = (uint32_t)__cvta_generic_to_shared(Bbuf);

    int t = threadIdx.x;
    int lane = t & 31, wid = t >> 5;
    int wm = wid & 1, wn = wid >> 1;     // 2 x 4 warp grid, warp tile 64x32
    int g = lane >> 2, tg = lane & 3;
    int row0 = (blockIdx.x >> 1) * 128;
    int col0 = (blockIdx.x & 1) * 128;

    // ldmatrix per-lane base offsets (in halves)
    uint32_t a_off[4];
#pragma unroll
    for (int mf = 0; mf < 4; mf++) {
        int rowA = wm * 64 + mf * 16 + (lane & 15);
        int colA = ((lane >> 4) << 3);
        a_off[mf] = rowA * SMS_H + colA;
    }
    uint32_t b_off[2];
#pragma unroll
    for (int nfp = 0; nfp < 2; nfp++) {
        int rowB = wn * 32 + nfp * 16 + (lane & 7) + ((lane >> 4) << 3);
        int colB = (((lane >> 3) & 1) << 3);
        b_off[nfp] = rowB * SMS_H + colB;
    }

    const int nch = K >> 5;

    auto issue = [&](int kc, int stg) {
        int k0 = kc << 5;
        uint32_t sa = sA0 + stg * (TILE_AH * 2);
        uint32_t sb = sB0 + stg * (TILE_BH * 2);
#pragma unroll
        for (int q = 0; q < 2; q++) {
            int idx = t + (q << 8);
            int r = idx >> 2, c8 = (idx & 3) << 3;
            int gr = row0 + r;
            const __half* srcA = A + (size_t)min(gr, M - 1) * K + k0 + c8;
            cpa16(sa + (r * SMS_H + c8) * 2, srcA, gr < M ? 16 : 0);
        }
#pragma unroll
        for (int q = 0; q < 2; q++) {
            int idx = t + (q << 8);
            int r = idx >> 2, c8 = (idx & 3) << 3;
            const __half* srcB = Bt + (size_t)(col0 + r) * K + k0 + c8;
            cpa16(sb + (r * SMS_H + c8) * 2, srcB, 16);
        }
        asm volatile("cp.async.commit_group;" ::: "memory");
    };

    float c[4][4][4] = {};
    issue(0, 0);
    issue(1, 1);

    for (int kc = 0; kc < nch; kc++) {
        int stg = kc % STAGES;
        if (kc + 2 < nch) {
            issue(kc + 2, (kc + 2) % STAGES);
            asm volatile("cp.async.wait_group 2;" ::: "memory");
        } else if (kc + 1 < nch) {
            asm volatile("cp.async.wait_group 1;" ::: "memory");
        } else {
            asm volatile("cp.async.wait_group 0;" ::: "memory");
        }
        __syncthreads();
        uint32_t saS = sA0 + stg * (TILE_AH * 2);
        uint32_t sbS = sB0 + stg * (TILE_BH * 2);
#pragma unroll
        for (int ks = 0; ks < 2; ks++) {
            int kb = ks * 16;
            uint32_t a[4][4], b[4][2];
#pragma unroll
            for (int mf = 0; mf < 4; mf++)
                LDSM_X4(a[mf][0], a[mf][1], a[mf][2], a[mf][3],
                        saS + (a_off[mf] + kb) * 2);
#pragma unroll
            for (int nfp = 0; nfp < 2; nfp++)
                LDSM_X4(b[2 * nfp][0], b[2 * nfp][1], b[2 * nfp + 1][0], b[2 * nfp + 1][1],
                        sbS + (b_off[nfp] + kb) * 2);
#pragma unroll
            for (int mf = 0; mf < 4; mf++)
#pragma unroll
                for (int nf = 0; nf < 4; nf++)
                    asm volatile(
                        "mma.sync.aligned.m16n8k16.row.col.f32.f16.f16.f32 "
                        "{%0,%1,%2,%3}, {%4,%5,%6,%7}, {%8,%9}, {%0,%1,%2,%3};"
                        : "+f"(c[mf][nf][0]), "+f"(c[mf][nf][1]),
                          "+f"(c[mf][nf][2]), "+f"(c[mf][nf][3])
                        : "r"(a[mf][0]), "r"(a[mf][1]), "r"(a[mf][2]), "r"(a[mf][3]),
                          "r"(b[nf][0]), "r"(b[nf][1]));
        }
        __syncthreads();
    }

    // epilogue: store C (fp16) + fused attention dots (warp cols within one head)
    int head = (col0 + wn * 32) >> 6;
#pragma unroll
    for (int mf = 0; mf < 4; mf++) {
        int r0 = row0 + wm * 64 + mf * 16 + g;
        int r1 = r0 + 8;
        float sv0 = 0.f, sv1 = 0.f, dv0 = 0.f, dv1 = 0.f;
#pragma unroll
        for (int nf = 0; nf < 4; nf++) {
            int col = col0 + wn * 32 + nf * 8 + tg * 2;
            float x0 = c[mf][nf][0], x1 = c[mf][nf][1];
            float x2 = c[mf][nf][2], x3 = c[mf][nf][3];
            if (r0 < M)
                *(__half2*)(C + (size_t)r0 * NCOLS + col) = __floats2half2_rn(x0, x1);
            if (r1 < M)
                *(__half2*)(C + (size_t)r1 * NCOLS + col) = __floats2half2_rn(x2, x3);
            float w0 = __ldg(avs + col), w1 = __ldg(avs + col + 1);
            float u0 = __ldg(avd + col), u1 = __ldg(avd + col + 1);
            sv0 += x0 * w0 + x1 * w1;
            sv1 += x2 * w0 + x3 * w1;
            dv0 += x0 * u0 + x1 * u1;
            dv1 += x2 * u0 + x3 * u1;
        }
        sv0 += __shfl_xor_sync(0xffffffffu, sv0, 1);
        sv0 += __shfl_xor_sync(0xffffffffu, sv0, 2);
        sv1 += __shfl_xor_sync(0xffffffffu, sv1, 1);
        sv1 += __shfl_xor_sync(0xffffffffu, sv1, 2);
        dv0 += __shfl_xor_sync(0xffffffffu, dv0, 1);
        dv0 += __shfl_xor_sync(0xffffffffu, dv0, 2);
        dv1 += __shfl_xor_sync(0xffffffffu, dv1, 1);
        dv1 += __shfl_xor_sync(0xffffffffu, dv1, 2);
        if (tg == 0) {
            // partial head dot (32 of 64 cols) -> atomic-free: two warps per head
            // band write disjoint halves? No: both halves belong to same head sum.
            // Use atomicAdd into zero-initialized? Instead: shfl across wn pairs via smem.
            // Simpler: atomicAdd (16 adds per row total, negligible).
            if (r0 < M) {
                atomicAdd(&g_asrc[r0 * 4 + head], sv0);
                atomicAdd(&g_adst[r0 * 4 + head], dv0);
            }
            if (r1 < M) {
                atomicAdd(&g_asrc[r1 * 4 + head], sv1);
                atomicAdd(&g_adst[r1 * 4 + head], dv1);
            }
        }
    }
}

// zero alpha buffers (needed since epilogue now accumulates atomically)
__global__ void zero_alpha_k() {
    int i = blockIdx.x * blockDim.x + threadIdx.x;
    if (i < N_NODES * 4) { g_asrc[i] = 0.f; g_adst[i] = 0.f; }
}

// ---------------- aggregation: one warp per dst, no-max softmax ------------------
__global__ __launch_bounds__(256) void aggr_k(
    const __half* __restrict__ h, const float* __restrict__ bias,
    __half* __restrict__ out_h, float* __restrict__ out_f)
{
    __shared__ float sw[8][128];
    int d    = (blockIdx.x * blockDim.x + threadIdx.x) >> 5;
    int lane = threadIdx.x & 31;
    int wblk = threadIdx.x >> 5;
    if (d >= N_NODES) return;
    int hol = lane >> 3;
    float* swp = sw[wblk];

    int beg = g_rowptr[d];
    int end = g_rowptr[d + 1];
    float4 adst4 = *(const float4*)(g_adst + d * 4);

    float wsum = 0.f;
    float4 acc0 = make_float4(0.f, 0.f, 0.f, 0.f);
    float4 acc1 = make_float4(0.f, 0.f, 0.f, 0.f);

    for (int base = beg; base < end; base += 32) {
        int i = base + lane;
        bool v = i < end;
        int s_l = v ? g_csr_src[i] : 0;
        float4 w4 = make_float4(0.f, 0.f, 0.f, 0.f);
        if (v) {
            float4 as4 = *(const float4*)(g_asrc + s_l * 4);
            float ex = as4.x + adst4.x, ey = as4.y + adst4.y;
            float ez = as4.z + adst4.z, ew = as4.w + adst4.w;
            ex = ex > 0.f ? ex : SLOPE * ex;
            ey = ey > 0.f ? ey : SLOPE * ey;
            ez = ez > 0.f ? ez : SLOPE * ez;
            ew = ew > 0.f ? ew : SLOPE * ew;
            w4.x = __expf(ex); w4.y = __expf(ey);
            w4.z = __expf(ez); w4.w = __expf(ew);
        }
        *(float4*)(swp + lane * 4) = w4;
        __syncwarp();

        int n = min(32, end - base);
        int j = 0;
        for (; j + 4 <= n; j += 4) {
            int s0 = __shfl_sync(0xffffffffu, s_l, j);
            int s1 = __shfl_sync(0xffffffffu, s_l, j + 1);
            int s2 = __shfl_sync(0xffffffffu, s_l, j + 2);
            int s3 = __shfl_sync(0xffffffffu, s_l, j + 3);
            float w0 = swp[j * 4 + hol];
            float w1 = swp[j * 4 + 4 + hol];
            float w2 = swp[j * 4 + 8 + hol];
            float w3 = swp[j * 4 + 12 + hol];
            wsum += (w0 + w1) + (w2 + w3);
            uint4 v0 = *(const uint4*)(h + (size_t)s0 * NCOLS + lane * 8);
            uint4 v1 = *(const uint4*)(h + (size_t)s1 * NCOLS + lane * 8);
            uint4 v2 = *(const uint4*)(h + (size_t)s2 * NCOLS + lane * 8);
            uint4 v3 = *(const uint4*)(h + (size_t)s3 * NCOLS + lane * 8);
            const __half2* p0 = (const __half2*)&v0;
            const __half2* p1 = (const __half2*)&v1;
            const __half2* p2 = (const __half2*)&v2;
            const __half2* p3 = (const __half2*)&v3;
#pragma unroll
            for (int q = 0; q < 2; q++) {
                float2 f0 = __half22float2(p0[q]), f0b = __half22float2(p0[q + 2]);
                float2 f1 = __half22float2(p1[q]), f1b = __half22float2(p1[q + 2]);
                float2 f2 = __half22float2(p2[q]), f2b = __half22float2(p2[q + 2]);
                float2 f3 = __half22float2(p3[q]), f3b = __half22float2(p3[q + 2]);
                float* a0 = (q == 0) ? &acc0.x : &acc0.z;
                float* a1 = (q == 0) ? &acc1.x : &acc1.z;
                a0[0] += w0 * f0.x + w1 * f1.x + w2 * f2.x + w3 * f3.x;
                a0[1] += w0 * f0.y + w1 * f1.y + w2 * f2.y + w3 * f3.y;
                a1[0] += w0 * f0b.x + w1 * f1b.x + w2 * f2b.x + w3 * f3b.x;
                a1[1] += w0 * f0b.y + w1 * f1b.y + w2 * f2b.y + w3 * f3b.y;
            }
        }
        for (; j < n; j++) {
            int s0 = __shfl_sync(0xffffffffu, s_l, j);
            float w0 = swp[j * 4 + hol];
            wsum += w0;
            uint4 v0 = *(const uint4*)(h + (size_t)s0 * NCOLS + lane * 8);
            const __half2* p0 = (const __half2*)&v0;
            float2 f0 = __half22float2(p0[0]);
            float2 f1 = __half22float2(p0[1]);
            float2 f2 = __half22float2(p0[2]);
            float2 f3 = __half22float2(p0[3]);
            acc0.x += w0 * f0.x; acc0.y += w0 * f0.y;
            acc0.z += w0 * f1.x; acc0.w += w0 * f1.y;
            acc1.x += w0 * f2.x; acc1.y += w0 * f2.y;
            acc1.z += w0 * f3.x; acc1.w += w0 * f3.y;
        }
        __syncwarp();
    }

    float inv = 1.f / wsum;
    int c0 = lane * 8;
    float4 bb0 = *(const float4*)(bias + c0);
    float4 bb1 = *(const float4*)(bias + c0 + 4);
    float o_[8];
    o_[0] = acc0.x * inv + bb0.x; o_[1] = acc0.y * inv + bb0.y;
    o_[2] = acc0.z * inv + bb0.z; o_[3] = acc0.w * inv + bb0.w;
    o_[4] = acc1.x * inv + bb1.x; o_[5] = acc1.y * inv + bb1.y;
    o_[6] = acc1.z * inv + bb1.z; o_[7] = acc1.w * inv + bb1.w;
#pragma unroll
    for (int k = 0; k < 8; k++) {
        float o = o_[k];
        o_[k] = o > 0.f ? o : (__expf(o) - 1.f);
    }
    if (out_h) {
        __half2 hh[4];
        hh[0] = __floats2half2_rn(o_[0], o_[1]);
        hh[1] = __floats2half2_rn(o_[2], o_[3]);
        hh[2] = __floats2half2_rn(o_[4], o_[5]);
        hh[3] = __floats2half2_rn(o_[6], o_[7]);
        *(uint4*)(out_h + (size_t)d * NCOLS + c0) = *(uint4*)hh;
    } else {
        *(float4*)(out_f + (size_t)d * NCOLS + c0)     = make_float4(o_[0], o_[1], o_[2], o_[3]);
        *(float4*)(out_f + (size_t)d * NCOLS + c0 + 4) = make_float4(o_[4], o_[5], o_[6], o_[7]);
    }
}

// ---------------- driver ---------------------------------------------------------
extern "C" void kernel_launch(void* const* d_in, const int* in_sizes, int n_in,
                              void* d_out, int out_size)
{
    const float* inp = (const float*)d_in[0];
    const int*   ei  = (const int*)d_in[1];
    const float* W1  = (const float*)d_in[2];
    const float* as1 = (const float*)d_in[3];
    const float* ad1 = (const float*)d_in[4];
    const float* b1  = (const float*)d_in[5];
    const float* W2  = (const float*)d_in[6];
    const float* as2 = (const float*)d_in[7];
    const float* ad2 = (const float*)d_in[8];
    const float* b2  = (const float*)d_in[9];
    const float* W3  = (const float*)d_in[10];
    const float* as3 = (const float*)d_in[11];
    const float* ad3 = (const float*)d_in[12];
    const float* b3  = (const float*)d_in[13];
    float* out = (float*)d_out;

    __half *hbuf, *xh, *bt1, *bt2, *bt3;
    int* counts;
    cudaGetSymbolAddress((void**)&hbuf, g_h);
    cudaGetSymbolAddress((void**)&xh, g_xh);
    cudaGetSymbolAddress((void**)&bt1, g_bt1);
    cudaGetSymbolAddress((void**)&bt2, g_bt2);
    cudaGetSymbolAddress((void**)&bt3, g_bt3);
    cudaGetSymbolAddress((void**)&counts, g_counts);

    cudaFuncSetAttribute(gemm_mma, cudaFuncAttributeMaxDynamicSharedMemorySize, GEMM_SMEM);

    static cudaStream_t s2 = nullptr;
    static cudaEvent_t e_fork = nullptr, e_join = nullptr;
    if (!s2) {
        cudaStreamCreateWithFlags(&s2, cudaStreamNonBlocking);
        cudaEventCreateWithFlags(&e_fork, cudaEventDisableTiming);
        cudaEventCreateWithFlags(&e_join, cudaEventDisableTiming);
    }

    int ggrid = 2 * ((N_NODES + 127) / 128);   // 782
    int agrid = (N_NODES * 32 + 255) / 256;
    int zgrid = (N_NODES * 4 + 255) / 256;

    cudaEventRecord(e_fork, 0);

    // main stream (kernel #4 = gemm -> ncu capture)
    transpose_h_k<<<(256 * 128 + 255) / 256, 256>>>(W1, bt1, 128);
    tohalf_k<<<(N_NODES * 128 + 255) / 256, 256>>>(inp, xh, N_NODES * 128);
    zero_alpha_k<<<zgrid, 256>>>();
    gemm_mma<<<ggrid, 256, GEMM_SMEM>>>(xh, bt1, hbuf, as1, ad1, N_NODES, 128);

    // fork stream: CSR build + W2/W3 transposes (only gate aggr1 / gemm2)
    cudaStreamWaitEvent(s2, e_fork, 0);
    cudaMemsetAsync(counts, 0, N_NODES * sizeof(int), s2);
    hist_k<<<(N_EDGES / 4 + 255) / 256, 256, 0, s2>>>(ei);
    scanA_k<<<NBLK, 256, 0, s2>>>();
    scanB_k<<<1, 256, 0, s2>>>();
    scanC_k<<<NBLK, 256, 0, s2>>>();
    scatter_k<<<(N_EDGES / 4 + 255) / 256, 256, 0, s2>>>(ei);
    transpose2_h_k<<<(2 * 256 * 256 + 255) / 256, 256, 0, s2>>>(W2, bt2, W3, bt3);
    cudaEventRecord(e_join, s2);

    cudaStreamWaitEvent(0, e_join, 0);
    aggr_k<<<agrid, 256>>>(hbuf, b1, xh, nullptr);

    zero_alpha_k<<<zgrid, 256>>>();
    gemm_mma<<<ggrid, 256, GEMM_SMEM>>>(xh, bt2, hbuf, as2, ad2, N_NODES, 256);
    aggr_k<<<agrid, 256>>>(hbuf, b2, xh, nullptr);

    zero_alpha_k<<<zgrid, 256>>>();
    gemm_mma<<<ggrid, 256, GEMM_SMEM>>>(xh, bt3, hbuf, as3, ad3, N_NODES, 256);
    aggr_k<<<agrid, 256>>>(hbuf, b3, nullptr, out);
}

// round 15
// speedup vs baseline: 1.0247x; 1.0046x over previous
#include <cuda_runtime.h>
#include <cuda_fp16.h>
#include <cstdint>

#define N_NODES 50000
#define N_EDGES 800000
#define E_TOT   (N_EDGES + N_NODES)
#define NCOLS   256
#define SLOPE   0.2f
#define NBLK    ((N_NODES + 255) / 256)

// ---------------- scratch (device globals) -----------------------------------
__device__ __half g_h[N_NODES * NCOLS];
__device__ __half g_xh[N_NODES * NCOLS];
__device__ __half g_bt1[256 * 128];
__device__ __half g_bt2[256 * 256];
__device__ __half g_bt3[256 * 256];
__device__ float  g_asrc[N_NODES * 4];
__device__ float  g_adst[N_NODES * 4];
__device__ int    g_counts[N_NODES];
__device__ int    g_bsum[256];
__device__ int    g_rowptr[N_NODES + 1];
__device__ int    g_cursor[N_NODES];
__device__ int    g_csr_src[E_TOT];

__device__ __forceinline__ void cpa16(uint32_t sdst, const void* gsrc, int srcsize) {
    asm volatile("cp.async.cg.shared.global [%0], [%1], 16, %2;"
                 :: "r"(sdst), "l"(gsrc), "r"(srcsize));
}
#define LDSM_X4(r0, r1, r2, r3, addr) \
    asm volatile("ldmatrix.sync.aligned.m8n8.x4.shared.b16 {%0,%1,%2,%3}, [%4];" \
                 : "=r"(r0), "=r"(r1), "=r"(r2), "=r"(r3) : "r"(addr))

// ---------------- CSR build (fast path) ------------------------------------------
__global__ void hist_k(const int* __restrict__ ei) {
    int q = blockIdx.x * blockDim.x + threadIdx.x;
    if (q * 4 >= N_EDGES) return;
    int4 d4 = *(const int4*)(ei + N_EDGES + q * 4);
    atomicAdd(&g_counts[d4.x], 1);
    atomicAdd(&g_counts[d4.y], 1);
    atomicAdd(&g_counts[d4.z], 1);
    atomicAdd(&g_counts[d4.w], 1);
}
__global__ void scanA_k() {
    __shared__ int sm[256];
    int i = blockIdx.x * 256 + threadIdx.x;
    int v = (i < N_NODES) ? g_counts[i] + 1 : 0;
    sm[threadIdx.x] = v;
    __syncthreads();
    for (int o = 128; o; o >>= 1) {
        if (threadIdx.x < o) sm[threadIdx.x] += sm[threadIdx.x + o];
        __syncthreads();
    }
    if (threadIdx.x == 0) g_bsum[blockIdx.x] = sm[0];
}
__global__ void scanB_k() {
    __shared__ int sm[256];
    int t = threadIdx.x;
    int v = (t < NBLK) ? g_bsum[t] : 0;
    sm[t] = v;
    __syncthreads();
    for (int o = 1; o < 256; o <<= 1) {
        int u = (t >= o) ? sm[t - o] : 0;
        __syncthreads();
        sm[t] += u;
        __syncthreads();
    }
    g_bsum[t] = sm[t] - v;
}
__global__ void scanC_k() {
    __shared__ int sm[256];
    int t = threadIdx.x;
    int i = blockIdx.x * 256 + t;
    int v = (i < N_NODES) ? g_counts[i] + 1 : 0;
    sm[t] = v;
    __syncthreads();
    for (int o = 1; o < 256; o <<= 1) {
        int u = (t >= o) ? sm[t - o] : 0;
        __syncthreads();
        sm[t] += u;
        __syncthreads();
    }
    if (i < N_NODES) {
        int off = g_bsum[blockIdx.x] + sm[t] - v;
        g_rowptr[i] = off;
        g_csr_src[off] = i;
        g_cursor[i] = off + 1;
    }
    if (i == 0) g_rowptr[N_NODES] = E_TOT;
}
__global__ void scatter_k(const int* __restrict__ ei) {
    int q = blockIdx.x * blockDim.x + threadIdx.x;
    if (q * 4 >= N_EDGES) return;
    int4 s4 = *(const int4*)(ei + q * 4);
    int4 d4 = *(const int4*)(ei + N_EDGES + q * 4);
    g_csr_src[atomicAdd(&g_cursor[d4.x], 1)] = s4.x;
    g_csr_src[atomicAdd(&g_cursor[d4.y], 1)] = s4.y;
    g_csr_src[atomicAdd(&g_cursor[d4.z], 1)] = s4.z;
    g_csr_src[atomicAdd(&g_cursor[d4.w], 1)] = s4.w;
}

// ---------------- prep kernels ---------------------------------------------------
__global__ void transpose_h_k(const float* __restrict__ W, __half* __restrict__ Bt, int K) {
    int idx = blockIdx.x * blockDim.x + threadIdx.x;
    if (idx >= 256 * K) return;
    int n = idx / K, k = idx - n * K;
    Bt[idx] = __float2half_rn(W[k * 256 + n]);
}
__global__ void transpose2_h_k(const float* __restrict__ W2, __half* __restrict__ Bt2,
                               const float* __restrict__ W3, __half* __restrict__ Bt3) {
    int idx = blockIdx.x * blockDim.x + threadIdx.x;
    const float* W = W2;
    __half* Bt = Bt2;
    if (idx >= 256 * 256) { idx -= 256 * 256; W = W3; Bt = Bt3; }
    int n = idx >> 8, k = idx & 255;
    Bt[idx] = __float2half_rn(W[k * 256 + n]);
}
__global__ void tohalf_k(const float* __restrict__ in, __half* __restrict__ o, int n) {
    int i = blockIdx.x * blockDim.x + threadIdx.x;
    if (i < n) o[i] = __float2half_rn(in[i]);
}

// ---------------- 4-stage cp.async fp16 GEMM, tile 128x128, 2 CTAs/SM ------------
// 256 threads, 2x4 warp grid, warp tile 64x32; alpha via smem pair-reduction.
#define SMS_H 40
#define TILE_AH (128 * SMS_H)
#define TILE_BH (128 * SMS_H)
#define STAGES 4
#define GEMM_SMEM (STAGES * (TILE_AH + TILE_BH) * 2)   // 81920 B -> 2 CTAs/SM

__global__ __launch_bounds__(256, 2) void gemm_mma(
    const __half* __restrict__ A, const __half* __restrict__ Bt,
    __half* __restrict__ C,
    const float* __restrict__ avs, const float* __restrict__ avd,
    int M, int K)
{
    extern __shared__ __half smh[];
    __half* Abuf = smh;
    __half* Bbuf = smh + STAGES * TILE_AH;
    uint32_t sA0 = (uint32_t)__cvta_generic_to_shared(Abuf);
    uint32_t sB0 = (uint32_t)__cvta_generic_to_shared(Bbuf);

    int t = threadIdx.x;
    int lane = t & 31, wid = t >> 5;
    int wm = wid & 1, wn = wid >> 1;     // 2 x 4 warp grid, warp tile 64x32
    int g = lane >> 2, tg = lane & 3;
    int row0 = (blockIdx.x >> 1) * 128;
    int col0 = (blockIdx.x & 1) * 128;

    uint32_t a_off[4];
#pragma unroll
    for (int mf = 0; mf < 4; mf++) {
        int rowA = wm * 64 + mf * 16 + (lane & 15);
        int colA = ((lane >> 4) << 3);
        a_off[mf] = rowA * SMS_H + colA;
    }
    uint32_t b_off[2];
#pragma unroll
    for (int nfp = 0; nfp < 2; nfp++) {
        int rowB = wn * 32 + nfp * 16 + (lane & 7) + ((lane >> 4) << 3);
        int colB = (((lane >> 3) & 1) << 3);
        b_off[nfp] = rowB * SMS_H + colB;
    }

    const int nch = K >> 5;

    auto issue = [&](int kc, int stg) {
        int k0 = kc << 5;
        uint32_t sa = sA0 + stg * (TILE_AH * 2);
        uint32_t sb = sB0 + stg * (TILE_BH * 2);
#pragma unroll
        for (int q = 0; q < 2; q++) {
            int idx = t + (q << 8);
            int r = idx >> 2, c8 = (idx & 3) << 3;
            int gr = row0 + r;
            const __half* srcA = A + (size_t)min(gr, M - 1) * K + k0 + c8;
            cpa16(sa + (r * SMS_H + c8) * 2, srcA, gr < M ? 16 : 0);
        }
#pragma unroll
        for (int q = 0; q < 2; q++) {
            int idx = t + (q << 8);
            int r = idx >> 2, c8 = (idx & 3) << 3;
            const __half* srcB = Bt + (size_t)(col0 + r) * K + k0 + c8;
            cpa16(sb + (r * SMS_H + c8) * 2, srcB, 16);
        }
        asm volatile("cp.async.commit_group;" ::: "memory");
    };

    float c[4][4][4] = {};
    issue(0, 0);
    issue(1, 1);
    issue(2, 2);

    for (int kc = 0; kc < nch; kc++) {
        int stg = kc & 3;
        if (kc + 3 < nch) {
            issue(kc + 3, (kc + 3) & 3);
            asm volatile("cp.async.wait_group 3;" ::: "memory");
        } else if (kc + 2 < nch) {
            asm volatile("cp.async.wait_group 2;" ::: "memory");
        } else if (kc + 1 < nch) {
            asm volatile("cp.async.wait_group 1;" ::: "memory");
        } else {
            asm volatile("cp.async.wait_group 0;" ::: "memory");
        }
        __syncthreads();
        uint32_t saS = sA0 + stg * (TILE_AH * 2);
        uint32_t sbS = sB0 + stg * (TILE_BH * 2);
#pragma unroll
        for (int ks = 0; ks < 2; ks++) {
            int kb = ks * 16;
            uint32_t a[4][4], b[4][2];
#pragma unroll
            for (int mf = 0; mf < 4; mf++)
                LDSM_X4(a[mf][0], a[mf][1], a[mf][2], a[mf][3],
                        saS + (a_off[mf] + kb) * 2);
#pragma unroll
            for (int nfp = 0; nfp < 2; nfp++)
                LDSM_X4(b[2 * nfp][0], b[2 * nfp][1], b[2 * nfp + 1][0], b[2 * nfp + 1][1],
                        sbS + (b_off[nfp] + kb) * 2);
#pragma unroll
            for (int mf = 0; mf < 4; mf++)
#pragma unroll
                for (int nf = 0; nf < 4; nf++)
                    asm volatile(
                        "mma.sync.aligned.m16n8k16.row.col.f32.f16.f16.f32 "
                        "{%0,%1,%2,%3}, {%4,%5,%6,%7}, {%8,%9}, {%0,%1,%2,%3};"
                        : "+f"(c[mf][nf][0]), "+f"(c[mf][nf][1]),
                          "+f"(c[mf][nf][2]), "+f"(c[mf][nf][3])
                        : "r"(a[mf][0]), "r"(a[mf][1]), "r"(a[mf][2]), "r"(a[mf][3]),
                          "r"(b[nf][0]), "r"(b[nf][1]));
        }
        __syncthreads();
    }

    // epilogue: store C (fp16), stage per-warp alpha partials in smem
    float4* sred = (float4*)smh;   // 8 warps x 4 mf x 8 g = 256 float4 (4 KB)
#pragma unroll
    for (int mf = 0; mf < 4; mf++) {
        int r0 = row0 + wm * 64 + mf * 16 + g;
        int r1 = r0 + 8;
        float sv0 = 0.f, sv1 = 0.f, dv0 = 0.f, dv1 = 0.f;
#pragma unroll
        for (int nf = 0; nf < 4; nf++) {
            int col = col0 + wn * 32 + nf * 8 + tg * 2;
            float x0 = c[mf][nf][0], x1 = c[mf][nf][1];
            float x2 = c[mf][nf][2], x3 = c[mf][nf][3];
            if (r0 < M)
                *(__half2*)(C + (size_t)r0 * NCOLS + col) = __floats2half2_rn(x0, x1);
            if (r1 < M)
                *(__half2*)(C + (size_t)r1 * NCOLS + col) = __floats2half2_rn(x2, x3);
            float w0 = __ldg(avs + col), w1 = __ldg(avs + col + 1);
            float u0 = __ldg(avd + col), u1 = __ldg(avd + col + 1);
            sv0 += x0 * w0 + x1 * w1;
            sv1 += x2 * w0 + x3 * w1;
            dv0 += x0 * u0 + x1 * u1;
            dv1 += x2 * u0 + x3 * u1;
        }
        sv0 += __shfl_xor_sync(0xffffffffu, sv0, 1);
        sv0 += __shfl_xor_sync(0xffffffffu, sv0, 2);
        sv1 += __shfl_xor_sync(0xffffffffu, sv1, 1);
        sv1 += __shfl_xor_sync(0xffffffffu, sv1, 2);
        dv0 += __shfl_xor_sync(0xffffffffu, dv0, 1);
        dv0 += __shfl_xor_sync(0xffffffffu, dv0, 2);
        dv1 += __shfl_xor_sync(0xffffffffu, dv1, 1);
        dv1 += __shfl_xor_sync(0xffffffffu, dv1, 2);
        if (tg == 0)
            sred[(wid * 4 + mf) * 8 + g] = make_float4(sv0, dv0, sv1, dv1);
    }
    __syncthreads();
    // combine partner-warp partials (wn and wn^1 cover the two halves of a head)
    if (!(wn & 1) && tg == 0) {
        int pwid = ((wn ^ 1) << 1) | wm;
        int head = (col0 >> 6) + (wn >> 1);
#pragma unroll
        for (int mf = 0; mf < 4; mf++) {
            float4 pa = sred[(wid * 4 + mf) * 8 + g];
            float4 pb = sred[(pwid * 4 + mf) * 8 + g];
            int r0 = row0 + wm * 64 + mf * 16 + g;
            int r1 = r0 + 8;
            if (r0 < M) {
                g_asrc[r0 * 4 + head] = pa.x + pb.x;
                g_adst[r0 * 4 + head] = pa.y + pb.y;
            }
            if (r1 < M) {
                g_asrc[r1 * 4 + head] = pa.z + pb.z;
                g_adst[r1 * 4 + head] = pa.w + pb.w;
            }
        }
    }
}

// ---------------- aggregation: one warp per dst, no-max softmax ------------------
__global__ __launch_bounds__(256) void aggr_k(
    const __half* __restrict__ h, const float* __restrict__ bias,
    __half* __restrict__ out_h, float* __restrict__ out_f)
{
    __shared__ float sw[8][128];
    int d    = (blockIdx.x * blockDim.x + threadIdx.x) >> 5;
    int lane = threadIdx.x & 31;
    int wblk = threadIdx.x >> 5;
    if (d >= N_NODES) return;
    int hol = lane >> 3;
    float* swp = sw[wblk];

    int beg = g_rowptr[d];
    int end = g_rowptr[d + 1];
    float4 adst4 = *(const float4*)(g_adst + d * 4);

    float wsum = 0.f;
    float4 acc0 = make_float4(0.f, 0.f, 0.f, 0.f);
    float4 acc1 = make_float4(0.f, 0.f, 0.f, 0.f);

    for (int base = beg; base < end; base += 32) {
        int i = base + lane;
        bool v = i < end;
        int s_l = v ? g_csr_src[i] : 0;
        float4 w4 = make_float4(0.f, 0.f, 0.f, 0.f);
        if (v) {
            float4 as4 = *(const float4*)(g_asrc + s_l * 4);
            float ex = as4.x + adst4.x, ey = as4.y + adst4.y;
            float ez = as4.z + adst4.z, ew = as4.w + adst4.w;
            ex = ex > 0.f ? ex : SLOPE * ex;
            ey = ey > 0.f ? ey : SLOPE * ey;
            ez = ez > 0.f ? ez : SLOPE * ez;
            ew = ew > 0.f ? ew : SLOPE * ew;
            w4.x = __expf(ex); w4.y = __expf(ey);
            w4.z = __expf(ez); w4.w = __expf(ew);
        }
        *(float4*)(swp + lane * 4) = w4;
        __syncwarp();

        int n = min(32, end - base);
        int j = 0;
        for (; j + 4 <= n; j += 4) {
            int s0 = __shfl_sync(0xffffffffu, s_l, j);
            int s1 = __shfl_sync(0xffffffffu, s_l, j + 1);
            int s2 = __shfl_sync(0xffffffffu, s_l, j + 2);
            int s3 = __shfl_sync(0xffffffffu, s_l, j + 3);
            float w0 = swp[j * 4 + hol];
            float w1 = swp[j * 4 + 4 + hol];
            float w2 = swp[j * 4 + 8 + hol];
            float w3 = swp[j * 4 + 12 + hol];
            wsum += (w0 + w1) + (w2 + w3);
            uint4 v0 = *(const uint4*)(h + (size_t)s0 * NCOLS + lane * 8);
            uint4 v1 = *(const uint4*)(h + (size_t)s1 * NCOLS + lane * 8);
            uint4 v2 = *(const uint4*)(h + (size_t)s2 * NCOLS + lane * 8);
            uint4 v3 = *(const uint4*)(h + (size_t)s3 * NCOLS + lane * 8);
            const __half2* p0 = (const __half2*)&v0;
            const __half2* p1 = (const __half2*)&v1;
            const __half2* p2 = (const __half2*)&v2;
            const __half2* p3 = (const __half2*)&v3;
#pragma unroll
            for (int q = 0; q < 2; q++) {
                float2 f0 = __half22float2(p0[q]), f0b = __half22float2(p0[q + 2]);
                float2 f1 = __half22float2(p1[q]), f1b = __half22float2(p1[q + 2]);
                float2 f2 = __half22float2(p2[q]), f2b = __half22float2(p2[q + 2]);
                float2 f3 = __half22float2(p3[q]), f3b = __half22float2(p3[q + 2]);
                float* a0 = (q == 0) ? &acc0.x : &acc0.z;
                float* a1 = (q == 0) ? &acc1.x : &acc1.z;
                a0[0] += w0 * f0.x + w1 * f1.x + w2 * f2.x + w3 * f3.x;
                a0[1] += w0 * f0.y + w1 * f1.y + w2 * f2.y + w3 * f3.y;
                a1[0] += w0 * f0b.x + w1 * f1b.x + w2 * f2b.x + w3 * f3b.x;
                a1[1] += w0 * f0b.y + w1 * f1b.y + w2 * f2b.y + w3 * f3b.y;
            }
        }
        for (; j < n; j++) {
            int s0 = __shfl_sync(0xffffffffu, s_l, j);
            float w0 = swp[j * 4 + hol];
            wsum += w0;
            uint4 v0 = *(const uint4*)(h + (size_t)s0 * NCOLS + lane * 8);
            const __half2* p0 = (const __half2*)&v0;
            float2 f0 = __half22float2(p0[0]);
            float2 f1 = __half22float2(p0[1]);
            float2 f2 = __half22float2(p0[2]);
            float2 f3 = __half22float2(p0[3]);
            acc0.x += w0 * f0.x; acc0.y += w0 * f0.y;
            acc0.z += w0 * f1.x; acc0.w += w0 * f1.y;
            acc1.x += w0 * f2.x; acc1.y += w0 * f2.y;
            acc1.z += w0 * f3.x; acc1.w += w0 * f3.y;
        }
        __syncwarp();
    }

    float inv = 1.f / (hol == 0 ? wsum : (hol == 1 ? wsum : wsum));
    inv = 1.f / wsum;
    int c0 = lane * 8;
    float4 bb0 = *(const float4*)(bias + c0);
    float4 bb1 = *(const float4*)(bias + c0 + 4);
    float o_[8];
    o_[0] = acc0.x * inv + bb0.x; o_[1] = acc0.y * inv + bb0.y;
    o_[2] = acc0.z * inv + bb0.z; o_[3] = acc0.w * inv + bb0.w;
    o_[4] = acc1.x * inv + bb1.x; o_[5] = acc1.y * inv + bb1.y;
    o_[6] = acc1.z * inv + bb1.z; o_[7] = acc1.w * inv + bb1.w;
#pragma unroll
    for (int k = 0; k < 8; k++) {
        float o = o_[k];
        o_[k] = o > 0.f ? o : (__expf(o) - 1.f);
    }
    if (out_h) {
        __half2 hh[4];
        hh[0] = __floats2half2_rn(o_[0], o_[1]);
        hh[1] = __floats2half2_rn(o_[2], o_[3]);
        hh[2] = __floats2half2_rn(o_[4], o_[5]);
        hh[3] = __floats2half2_rn(o_[6], o_[7]);
        *(uint4*)(out_h + (size_t)d * NCOLS + c0) = *(uint4*)hh;
    } else {
        *(float4*)(out_f + (size_t)d * NCOLS + c0)     = make_float4(o_[0], o_[1], o_[2], o_[3]);
        *(float4*)(out_f + (size_t)d * NCOLS + c0 + 4) = make_float4(o_[4], o_[5], o_[6], o_[7]);
    }
}

// ---------------- driver ---------------------------------------------------------
extern "C" void kernel_launch(void* const* d_in, const int* in_sizes, int n_in,
                              void* d_out, int out_size)
{
    const float* inp = (const float*)d_in[0];
    const int*   ei  = (const int*)d_in[1];
    const float* W1  = (const float*)d_in[2];
    const float* as1 = (const float*)d_in[3];
    const float* ad1 = (const float*)d_in[4];
    const float* b1  = (const float*)d_in[5];
    const float* W2  = (const float*)d_in[6];
    const float* as2 = (const float*)d_in[7];
    const float* ad2 = (const float*)d_in[8];
    const float* b2  = (const float*)d_in[9];
    const float* W3  = (const float*)d_in[10];
    const float* as3 = (const float*)d_in[11];
    const float* ad3 = (const float*)d_in[12];
    const float* b3  = (const float*)d_in[13];
    float* out = (float*)d_out;

    __half *hbuf, *xh, *bt1, *bt2, *bt3;
    int* counts;
    cudaGetSymbolAddress((void**)&hbuf, g_h);
    cudaGetSymbolAddress((void**)&xh, g_xh);
    cudaGetSymbolAddress((void**)&bt1, g_bt1);
    cudaGetSymbolAddress((void**)&bt2, g_bt2);
    cudaGetSymbolAddress((void**)&bt3, g_bt3);
    cudaGetSymbolAddress((void**)&counts, g_counts);

    cudaFuncSetAttribute(gemm_mma, cudaFuncAttributeMaxDynamicSharedMemorySize, GEMM_SMEM);

    static cudaStream_t s2 = nullptr;
    static cudaEvent_t e_fork = nullptr, e_join = nullptr;
    if (!s2) {
        cudaStreamCreateWithFlags(&s2, cudaStreamNonBlocking);
        cudaEventCreateWithFlags(&e_fork, cudaEventDisableTiming);
        cudaEventCreateWithFlags(&e_join, cudaEventDisableTiming);
    }

    int ggrid = 2 * ((N_NODES + 127) / 128);   // 782
    int agrid = (N_NODES * 32 + 255) / 256;

    cudaEventRecord(e_fork, 0);

    // main stream (kernel #4 = gemm -> ncu capture)
    transpose_h_k<<<(256 * 128 + 255) / 256, 256>>>(W1, bt1, 128);
    tohalf_k<<<(N_NODES * 128 + 255) / 256, 256>>>(inp, xh, N_NODES * 128);
    transpose2_h_k<<<(2 * 256 * 256 + 255) / 256, 256>>>(W2, bt2, W3, bt3);
    gemm_mma<<<ggrid, 256, GEMM_SMEM>>>(xh, bt1, hbuf, as1, ad1, N_NODES, 128);

    // fork stream: CSR build (only gates aggr1)
    cudaStreamWaitEvent(s2, e_fork, 0);
    cudaMemsetAsync(counts, 0, N_NODES * sizeof(int), s2);
    hist_k<<<(N_EDGES / 4 + 255) / 256, 256, 0, s2>>>(ei);
    scanA_k<<<NBLK, 256, 0, s2>>>();
    scanB_k<<<1, 256, 0, s2>>>();
    scanC_k<<<NBLK, 256, 0, s2>>>();
    scatter_k<<<(N_EDGES / 4 + 255) / 256, 256, 0, s2>>>(ei);
    cudaEventRecord(e_join, s2);

    cudaStreamWaitEvent(0, e_join, 0);
    aggr_k<<<agrid, 256>>>(hbuf, b1, xh, nullptr);

    gemm_mma<<<ggrid, 256, GEMM_SMEM>>>(xh, bt2, hbuf, as2, ad2, N_NODES, 256);
    aggr_k<<<agrid, 256>>>(hbuf, b2, xh, nullptr);

    gemm_mma<<<ggrid, 256, GEMM_SMEM>>>(xh, bt3, hbuf, as3, ad3, N_NODES, 256);
    aggr_k<<<agrid, 256>>>(hbuf, b3, nullptr, out);
}

// round 16
// speedup vs baseline: 1.0722x; 1.0463x over previous
#include <cuda_runtime.h>
#include <cuda_fp16.h>
#include <cstdint>

#define N_NODES 50000
#define N_EDGES 800000
#define E_TOT   (N_EDGES + N_NODES)
#define NCOLS   256
#define SLOPE   0.2f
#define NBLK    ((N_NODES + 255) / 256)

// ---------------- scratch (device globals) -----------------------------------
__device__ __half g_h[N_NODES * NCOLS];
__device__ __half g_xh[N_NODES * NCOLS];
__device__ __half g_bt1[256 * 128];
__device__ __half g_bt2[256 * 256];
__device__ __half g_bt3[256 * 256];
__device__ float  g_asrc[N_NODES * 4];
__device__ float  g_adst[N_NODES * 4];
__device__ int    g_counts[N_NODES];
__device__ int    g_bsum[256];
__device__ int    g_rowptr[N_NODES + 1];
__device__ int    g_cursor[N_NODES];
__device__ int    g_csr_src[E_TOT];

__device__ __forceinline__ void cpa16(uint32_t sdst, const void* gsrc, int srcsize) {
    asm volatile("cp.async.cg.shared.global [%0], [%1], 16, %2;"
                 :: "r"(sdst), "l"(gsrc), "r"(srcsize));
}
#define LDSM_X4(r0, r1, r2, r3, addr) \
    asm volatile("ldmatrix.sync.aligned.m8n8.x4.shared.b16 {%0,%1,%2,%3}, [%4];" \
                 : "=r"(r0), "=r"(r1), "=r"(r2), "=r"(r3) : "r"(addr))

// ---------------- CSR build (fast path) ------------------------------------------
__global__ void hist_k(const int* __restrict__ ei) {
    int q = blockIdx.x * blockDim.x + threadIdx.x;
    if (q * 4 >= N_EDGES) return;
    int4 d4 = *(const int4*)(ei + N_EDGES + q * 4);
    atomicAdd(&g_counts[d4.x], 1);
    atomicAdd(&g_counts[d4.y], 1);
    atomicAdd(&g_counts[d4.z], 1);
    atomicAdd(&g_counts[d4.w], 1);
}
__global__ void scanA_k() {
    __shared__ int sm[256];
    int i = blockIdx.x * 256 + threadIdx.x;
    int v = (i < N_NODES) ? g_counts[i] + 1 : 0;
    sm[threadIdx.x] = v;
    __syncthreads();
    for (int o = 128; o; o >>= 1) {
        if (threadIdx.x < o) sm[threadIdx.x] += sm[threadIdx.x + o];
        __syncthreads();
    }
    if (threadIdx.x == 0) g_bsum[blockIdx.x] = sm[0];
}
__global__ void scanB_k() {
    __shared__ int sm[256];
    int t = threadIdx.x;
    int v = (t < NBLK) ? g_bsum[t] : 0;
    sm[t] = v;
    __syncthreads();
    for (int o = 1; o < 256; o <<= 1) {
        int u = (t >= o) ? sm[t - o] : 0;
        __syncthreads();
        sm[t] += u;
        __syncthreads();
    }
    g_bsum[t] = sm[t] - v;
}
__global__ void scanC_k() {
    __shared__ int sm[256];
    int t = threadIdx.x;
    int i = blockIdx.x * 256 + t;
    int v = (i < N_NODES) ? g_counts[i] + 1 : 0;
    sm[t] = v;
    __syncthreads();
    for (int o = 1; o < 256; o <<= 1) {
        int u = (t >= o) ? sm[t - o] : 0;
        __syncthreads();
        sm[t] += u;
        __syncthreads();
    }
    if (i < N_NODES) {
        int off = g_bsum[blockIdx.x] + sm[t] - v;
        g_rowptr[i] = off;
        g_csr_src[off] = i;
        g_cursor[i] = off + 1;
    }
    if (i == 0) g_rowptr[N_NODES] = E_TOT;
}
__global__ void scatter_k(const int* __restrict__ ei) {
    int q = blockIdx.x * blockDim.x + threadIdx.x;
    if (q * 4 >= N_EDGES) return;
    int4 s4 = *(const int4*)(ei + q * 4);
    int4 d4 = *(const int4*)(ei + N_EDGES + q * 4);
    g_csr_src[atomicAdd(&g_cursor[d4.x], 1)] = s4.x;
    g_csr_src[atomicAdd(&g_cursor[d4.y], 1)] = s4.y;
    g_csr_src[atomicAdd(&g_cursor[d4.z], 1)] = s4.z;
    g_csr_src[atomicAdd(&g_cursor[d4.w], 1)] = s4.w;
}

// ---------------- fused prep: tohalf(x) + W1/W2/W3 transposes --------------------
#define N_X4 (N_NODES * 128 / 4)   // 1,600,000 float4 groups
__global__ void prep_k(const float* __restrict__ inp,
                       const float* __restrict__ W1,
                       const float* __restrict__ W2,
                       const float* __restrict__ W3)
{
    int i = blockIdx.x * blockDim.x + threadIdx.x;
    if (i < N_X4) {
        float4 v = *(const float4*)(inp + (size_t)i * 4);
        __half2 h0 = __floats2half2_rn(v.x, v.y);
        __half2 h1 = __floats2half2_rn(v.z, v.w);
        uint2 u = make_uint2(*(uint32_t*)&h0, *(uint32_t*)&h1);
        *(uint2*)(g_xh + (size_t)i * 4) = u;
        return;
    }
    i -= N_X4;
    if (i < 256 * 128) {
        int n = i >> 7, k = i & 127;
        g_bt1[i] = __float2half_rn(W1[k * 256 + n]);
        return;
    }
    i -= 256 * 128;
    if (i < 256 * 256) {
        int n = i >> 8, k = i & 255;
        g_bt2[i] = __float2half_rn(W2[k * 256 + n]);
        return;
    }
    i -= 256 * 256;
    if (i < 256 * 256) {
        int n = i >> 8, k = i & 255;
        g_bt3[i] = __float2half_rn(W3[k * 256 + n]);
    }
}
#define PREP_TOTAL (N_X4 + 256 * 128 + 2 * 256 * 256)

// ---------------- 3-stage cp.async fp16 GEMM, tile 128x128, 2 CTAs/SM ------------
#define SMS_H 40
#define TILE_AH (128 * SMS_H)
#define TILE_BH (128 * SMS_H)
#define STAGES 3
#define GEMM_SMEM (STAGES * (TILE_AH + TILE_BH) * 2)   // 61440 B -> 2 CTAs/SM

__global__ __launch_bounds__(256, 2) void gemm_mma(
    const __half* __restrict__ A, const __half* __restrict__ Bt,
    __half* __restrict__ C,
    const float* __restrict__ avs, const float* __restrict__ avd,
    int M, int K)
{
    extern __shared__ __half smh[];
    __half* Abuf = smh;
    __half* Bbuf = smh + STAGES * TILE_AH;
    uint32_t sA0 = (uint32_t)__cvta_generic_to_shared(Abuf);
    uint32_t sB0 = (uint32_t)__cvta_generic_to_shared(Bbuf);

    int t = threadIdx.x;
    int lane = t & 31, wid = t >> 5;
    int wm = wid & 1, wn = wid >> 1;
    int g = lane >> 2, tg = lane & 3;
    int row0 = (blockIdx.x >> 1) * 128;
    int col0 = (blockIdx.x & 1) * 128;

    uint32_t a_off[4];
#pragma unroll
    for (int mf = 0; mf < 4; mf++) {
        int rowA = wm * 64 + mf * 16 + (lane & 15);
        int colA = ((lane >> 4) << 3);
        a_off[mf] = rowA * SMS_H + colA;
    }
    uint32_t b_off[2];
#pragma unroll
    for (int nfp = 0; nfp < 2; nfp++) {
        int rowB = wn * 32 + nfp * 16 + (lane & 7) + ((lane >> 4) << 3);
        int colB = (((lane >> 3) & 1) << 3);
        b_off[nfp] = rowB * SMS_H + colB;
    }

    const int nch = K >> 5;

    auto issue = [&](int kc, int stg) {
        int k0 = kc << 5;
        uint32_t sa = sA0 + stg * (TILE_AH * 2);
        uint32_t sb = sB0 + stg * (TILE_BH * 2);
#pragma unroll
        for (int q = 0; q < 2; q++) {
            int idx = t + (q << 8);
            int r = idx >> 2, c8 = (idx & 3) << 3;
            int gr = row0 + r;
            const __half* srcA = A + (size_t)min(gr, M - 1) * K + k0 + c8;
            cpa16(sa + (r * SMS_H + c8) * 2, srcA, gr < M ? 16 : 0);
        }
#pragma unroll
        for (int q = 0; q < 2; q++) {
            int idx = t + (q << 8);
            int r = idx >> 2, c8 = (idx & 3) << 3;
            const __half* srcB = Bt + (size_t)(col0 + r) * K + k0 + c8;
            cpa16(sb + (r * SMS_H + c8) * 2, srcB, 16);
        }
        asm volatile("cp.async.commit_group;" ::: "memory");
    };

    float c[4][4][4] = {};
    issue(0, 0);
    issue(1, 1);

    for (int kc = 0; kc < nch; kc++) {
        int stg = kc % STAGES;
        if (kc + 2 < nch) {
            issue(kc + 2, (kc + 2) % STAGES);
            asm volatile("cp.async.wait_group 2;" ::: "memory");
        } else if (kc + 1 < nch) {
            asm volatile("cp.async.wait_group 1;" ::: "memory");
        } else {
            asm volatile("cp.async.wait_group 0;" ::: "memory");
        }
        __syncthreads();
        uint32_t saS = sA0 + stg * (TILE_AH * 2);
        uint32_t sbS = sB0 + stg * (TILE_BH * 2);
#pragma unroll
        for (int ks = 0; ks < 2; ks++) {
            int kb = ks * 16;
            uint32_t a[4][4], b[4][2];
#pragma unroll
            for (int mf = 0; mf < 4; mf++)
                LDSM_X4(a[mf][0], a[mf][1], a[mf][2], a[mf][3],
                        saS + (a_off[mf] + kb) * 2);
#pragma unroll
            for (int nfp = 0; nfp < 2; nfp++)
                LDSM_X4(b[2 * nfp][0], b[2 * nfp][1], b[2 * nfp + 1][0], b[2 * nfp + 1][1],
                        sbS + (b_off[nfp] + kb) * 2);
#pragma unroll
            for (int mf = 0; mf < 4; mf++)
#pragma unroll
                for (int nf = 0; nf < 4; nf++)
                    asm volatile(
                        "mma.sync.aligned.m16n8k16.row.col.f32.f16.f16.f32 "
                        "{%0,%1,%2,%3}, {%4,%5,%6,%7}, {%8,%9}, {%0,%1,%2,%3};"
                        : "+f"(c[mf][nf][0]), "+f"(c[mf][nf][1]),
                          "+f"(c[mf][nf][2]), "+f"(c[mf][nf][3])
                        : "r"(a[mf][0]), "r"(a[mf][1]), "r"(a[mf][2]), "r"(a[mf][3]),
                          "r"(b[nf][0]), "r"(b[nf][1]));
        }
        __syncthreads();
    }

    // epilogue: store C (fp16), alpha partials via smem pair-reduction
    float4* sred = (float4*)smh;   // 8 warps x 4 mf x 8 g = 256 float4 (4 KB)
#pragma unroll
    for (int mf = 0; mf < 4; mf++) {
        int r0 = row0 + wm * 64 + mf * 16 + g;
        int r1 = r0 + 8;
        float sv0 = 0.f, sv1 = 0.f, dv0 = 0.f, dv1 = 0.f;
#pragma unroll
        for (int nf = 0; nf < 4; nf++) {
            int col = col0 + wn * 32 + nf * 8 + tg * 2;
            float x0 = c[mf][nf][0], x1 = c[mf][nf][1];
            float x2 = c[mf][nf][2], x3 = c[mf][nf][3];
            if (r0 < M)
                *(__half2*)(C + (size_t)r0 * NCOLS + col) = __floats2half2_rn(x0, x1);
            if (r1 < M)
                *(__half2*)(C + (size_t)r1 * NCOLS + col) = __floats2half2_rn(x2, x3);
            float w0 = __ldg(avs + col), w1 = __ldg(avs + col + 1);
            float u0 = __ldg(avd + col), u1 = __ldg(avd + col + 1);
            sv0 += x0 * w0 + x1 * w1;
            sv1 += x2 * w0 + x3 * w1;
            dv0 += x0 * u0 + x1 * u1;
            dv1 += x2 * u0 + x3 * u1;
        }
        sv0 += __shfl_xor_sync(0xffffffffu, sv0, 1);
        sv0 += __shfl_xor_sync(0xffffffffu, sv0, 2);
        sv1 += __shfl_xor_sync(0xffffffffu, sv1, 1);
        sv1 += __shfl_xor_sync(0xffffffffu, sv1, 2);
        dv0 += __shfl_xor_sync(0xffffffffu, dv0, 1);
        dv0 += __shfl_xor_sync(0xffffffffu, dv0, 2);
        dv1 += __shfl_xor_sync(0xffffffffu, dv1, 1);
        dv1 += __shfl_xor_sync(0xffffffffu, dv1, 2);
        if (tg == 0)
            sred[(wid * 4 + mf) * 8 + g] = make_float4(sv0, dv0, sv1, dv1);
    }
    __syncthreads();
    if (!(wn & 1) && tg == 0) {
        int pwid = ((wn ^ 1) << 1) | wm;
        int head = (col0 >> 6) + (wn >> 1);
#pragma unroll
        for (int mf = 0; mf < 4; mf++) {
            float4 pa = sred[(wid * 4 + mf) * 8 + g];
            float4 pb = sred[(pwid * 4 + mf) * 8 + g];
            int r0 = row0 + wm * 64 + mf * 16 + g;
            int r1 = r0 + 8;
            if (r0 < M) {
                g_asrc[r0 * 4 + head] = pa.x + pb.x;
                g_adst[r0 * 4 + head] = pa.y + pb.y;
            }
            if (r1 < M) {
                g_asrc[r1 * 4 + head] = pa.z + pb.z;
                g_adst[r1 * 4 + head] = pa.w + pb.w;
            }
        }
    }
}

// ---------------- aggregation: one warp per dst, no-max softmax ------------------
__global__ __launch_bounds__(256) void aggr_k(
    const __half* __restrict__ h, const float* __restrict__ bias,
    __half* __restrict__ out_h, float* __restrict__ out_f)
{
    __shared__ float sw[8][128];
    int d    = (blockIdx.x * blockDim.x + threadIdx.x) >> 5;
    int lane = threadIdx.x & 31;
    int wblk = threadIdx.x >> 5;
    if (d >= N_NODES) return;
    int hol = lane >> 3;
    float* swp = sw[wblk];

    int beg = g_rowptr[d];
    int end = g_rowptr[d + 1];
    float4 adst4 = *(const float4*)(g_adst + d * 4);

    float wsum = 0.f;
    float4 acc0 = make_float4(0.f, 0.f, 0.f, 0.f);
    float4 acc1 = make_float4(0.f, 0.f, 0.f, 0.f);

    for (int base = beg; base < end; base += 32) {
        int i = base + lane;
        bool v = i < end;
        int s_l = v ? g_csr_src[i] : 0;
        float4 w4 = make_float4(0.f, 0.f, 0.f, 0.f);
        if (v) {
            float4 as4 = *(const float4*)(g_asrc + s_l * 4);
            float ex = as4.x + adst4.x, ey = as4.y + adst4.y;
            float ez = as4.z + adst4.z, ew = as4.w + adst4.w;
            ex = ex > 0.f ? ex : SLOPE * ex;
            ey = ey > 0.f ? ey : SLOPE * ey;
            ez = ez > 0.f ? ez : SLOPE * ez;
            ew = ew > 0.f ? ew : SLOPE * ew;
            w4.x = __expf(ex); w4.y = __expf(ey);
            w4.z = __expf(ez); w4.w = __expf(ew);
        }
        *(float4*)(swp + lane * 4) = w4;
        __syncwarp();

        int n = min(32, end - base);
        int j = 0;
        for (; j + 4 <= n; j += 4) {
            int s0 = __shfl_sync(0xffffffffu, s_l, j);
            int s1 = __shfl_sync(0xffffffffu, s_l, j + 1);
            int s2 = __shfl_sync(0xffffffffu, s_l, j + 2);
            int s3 = __shfl_sync(0xffffffffu, s_l, j + 3);
            float w0 = swp[j * 4 + hol];
            float w1 = swp[j * 4 + 4 + hol];
            float w2 = swp[j * 4 + 8 + hol];
            float w3 = swp[j * 4 + 12 + hol];
            wsum += (w0 + w1) + (w2 + w3);
            uint4 v0 = *(const uint4*)(h + (size_t)s0 * NCOLS + lane * 8);
            uint4 v1 = *(const uint4*)(h + (size_t)s1 * NCOLS + lane * 8);
            uint4 v2 = *(const uint4*)(h + (size_t)s2 * NCOLS + lane * 8);
            uint4 v3 = *(const uint4*)(h + (size_t)s3 * NCOLS + lane * 8);
            const __half2* p0 = (const __half2*)&v0;
            const __half2* p1 = (const __half2*)&v1;
            const __half2* p2 = (const __half2*)&v2;
            const __half2* p3 = (const __half2*)&v3;
#pragma unroll
            for (int q = 0; q < 2; q++) {
                float2 f0 = __half22float2(p0[q]), f0b = __half22float2(p0[q + 2]);
                float2 f1 = __half22float2(p1[q]), f1b = __half22float2(p1[q + 2]);
                float2 f2 = __half22float2(p2[q]), f2b = __half22float2(p2[q + 2]);
                float2 f3 = __half22float2(p3[q]), f3b = __half22float2(p3[q + 2]);
                float* a0 = (q == 0) ? &acc0.x : &acc0.z;
                float* a1 = (q == 0) ? &acc1.x : &acc1.z;
                a0[0] += w0 * f0.x + w1 * f1.x + w2 * f2.x + w3 * f3.x;
                a0[1] += w0 * f0.y + w1 * f1.y + w2 * f2.y + w3 * f3.y;
                a1[0] += w0 * f0b.x + w1 * f1b.x + w2 * f2b.x + w3 * f3b.x;
                a1[1] += w0 * f0b.y + w1 * f1b.y + w2 * f2b.y + w3 * f3b.y;
            }
        }
        for (; j < n; j++) {
            int s0 = __shfl_sync(0xffffffffu, s_l, j);
            float w0 = swp[j * 4 + hol];
            wsum += w0;
            uint4 v0 = *(const uint4*)(h + (size_t)s0 * NCOLS + lane * 8);
            const __half2* p0 = (const __half2*)&v0;
            float2 f0 = __half22float2(p0[0]);
            float2 f1 = __half22float2(p0[1]);
            float2 f2 = __half22float2(p0[2]);
            float2 f3 = __half22float2(p0[3]);
            acc0.x += w0 * f0.x; acc0.y += w0 * f0.y;
            acc0.z += w0 * f1.x; acc0.w += w0 * f1.y;
            acc1.x += w0 * f2.x; acc1.y += w0 * f2.y;
            acc1.z += w0 * f3.x; acc1.w += w0 * f3.y;
        }
        __syncwarp();
    }

    float inv = 1.f / wsum;
    int c0 = lane * 8;
    float4 bb0 = *(const float4*)(bias + c0);
    float4 bb1 = *(const float4*)(bias + c0 + 4);
    float o_[8];
    o_[0] = acc0.x * inv + bb0.x; o_[1] = acc0.y * inv + bb0.y;
    o_[2] = acc0.z * inv + bb0.z; o_[3] = acc0.w * inv + bb0.w;
    o_[4] = acc1.x * inv + bb1.x; o_[5] = acc1.y * inv + bb1.y;
    o_[6] = acc1.z * inv + bb1.z; o_[7] = acc1.w * inv + bb1.w;
#pragma unroll
    for (int k = 0; k < 8; k++) {
        float o = o_[k];
        o_[k] = o > 0.f ? o : (__expf(o) - 1.f);
    }
    if (out_h) {
        __half2 hh[4];
        hh[0] = __floats2half2_rn(o_[0], o_[1]);
        hh[1] = __floats2half2_rn(o_[2], o_[3]);
        hh[2] = __floats2half2_rn(o_[4], o_[5]);
        hh[3] = __floats2half2_rn(o_[6], o_[7]);
        *(uint4*)(out_h + (size_t)d * NCOLS + c0) = *(uint4*)hh;
    } else {
        *(float4*)(out_f + (size_t)d * NCOLS + c0)     = make_float4(o_[0], o_[1], o_[2], o_[3]);
        *(float4*)(out_f + (size_t)d * NCOLS + c0 + 4) = make_float4(o_[4], o_[5], o_[6], o_[7]);
    }
}

// ---------------- driver ---------------------------------------------------------
extern "C" void kernel_launch(void* const* d_in, const int* in_sizes, int n_in,
                              void* d_out, int out_size)
{
    const float* inp = (const float*)d_in[0];
    const int*   ei  = (const int*)d_in[1];
    const float* W1  = (const float*)d_in[2];
    const float* as1 = (const float*)d_in[3];
    const float* ad1 = (const float*)d_in[4];
    const float* b1  = (const float*)d_in[5];
    const float* W2  = (const float*)d_in[6];
    const float* as2 = (const float*)d_in[7];
    const float* ad2 = (const float*)d_in[8];
    const float* b2  = (const float*)d_in[9];
    const float* W3  = (const float*)d_in[10];
    const float* as3 = (const float*)d_in[11];
    const float* ad3 = (const float*)d_in[12];
    const float* b3  = (const float*)d_in[13];
    float* out = (float*)d_out;

    __half *hbuf, *xh, *bt1, *bt2, *bt3;
    int* counts;
    cudaGetSymbolAddress((void**)&hbuf, g_h);
    cudaGetSymbolAddress((void**)&xh, g_xh);
    cudaGetSymbolAddress((void**)&bt1, g_bt1);
    cudaGetSymbolAddress((void**)&bt2, g_bt2);
    cudaGetSymbolAddress((void**)&bt3, g_bt3);
    cudaGetSymbolAddress((void**)&counts, g_counts);

    cudaFuncSetAttribute(gemm_mma, cudaFuncAttributeMaxDynamicSharedMemorySize, GEMM_SMEM);

    static cudaStream_t s2 = nullptr;
    static cudaEvent_t e_fork = nullptr, e_join = nullptr;
    if (!s2) {
        cudaStreamCreateWithFlags(&s2, cudaStreamNonBlocking);
        cudaEventCreateWithFlags(&e_fork, cudaEventDisableTiming);
        cudaEventCreateWithFlags(&e_join, cudaEventDisableTiming);
    }

    int ggrid = 2 * ((N_NODES + 127) / 128);   // 782
    int agrid = (N_NODES * 32 + 255) / 256;

    cudaEventRecord(e_fork, 0);

    // main stream: fused prep + layer-1 GEMM
    prep_k<<<(PREP_TOTAL + 255) / 256, 256>>>(inp, W1, W2, W3);
    gemm_mma<<<ggrid, 256, GEMM_SMEM>>>(xh, bt1, hbuf, as1, ad1, N_NODES, 128);

    // fork stream: CSR build (only gates aggr1)
    cudaStreamWaitEvent(s2, e_fork, 0);
    cudaMemsetAsync(counts, 0, N_NODES * sizeof(int), s2);
    hist_k<<<(N_EDGES / 4 + 255) / 256, 256, 0, s2>>>(ei);
    scanA_k<<<NBLK, 256, 0, s2>>>();
    scanB_k<<<1, 256, 0, s2>>>();
    scanC_k<<<NBLK, 256, 0, s2>>>();
    scatter_k<<<(N_EDGES / 4 + 255) / 256, 256, 0, s2>>>(ei);
    cudaEventRecord(e_join, s2);

    cudaStreamWaitEvent(0, e_join, 0);
    aggr_k<<<agrid, 256>>>(hbuf, b1, xh, nullptr);

    gemm_mma<<<ggrid, 256, GEMM_SMEM>>>(xh, bt2, hbuf, as2, ad2, N_NODES, 256);
    aggr_k<<<agrid, 256>>>(hbuf, b2, xh, nullptr);

    gemm_mma<<<ggrid, 256, GEMM_SMEM>>>(xh, bt3, hbuf, as3, ad3, N_NODES, 256);
    aggr_k<<<agrid, 256>>>(hbuf, b3, nullptr, out);
}